// round 9
// baseline (speedup 1.0000x reference)
#include <cuda_runtime.h>
#include <cuda_bf16.h>
#include <cstdint>
#include <math.h>

#define N_MAX   100000
#define E_MAX   1600000
#define G_NUM   64

typedef unsigned long long ull;

// ---------------- scratch (device globals; no allocation) ----------------
__device__ __align__(16) float g_xl[N_MAX * 64];
__device__ __align__(16) float g_xr[N_MAX * 64];
__device__ __align__(16) float g_xs[N_MAX * 64];
__device__ __align__(16) float g_out[N_MAX * 64];
__device__ int   g_deg[N_MAX];
__device__ int   g_off[N_MAX];
__device__ int   g_cur[N_MAX];
__device__ int   g_csr[E_MAX];
__device__ int   g_bsum[1024];
__device__ float g_sumM[G_NUM * 64];   // later reused: cM
__device__ float g_sqM [G_NUM * 64];   // later reused: C
__device__ float g_sumS[G_NUM * 64];   // later reused: cS
__device__ float g_sqS [G_NUM * 64];
__device__ float g_cnt [G_NUM];

// ---------------- f32x2 helpers ----------------
__device__ __forceinline__ void fma2(ull& d, ull a, ull b) {
    asm("fma.rn.f32x2 %0, %1, %2, %0;" : "+l"(d) : "l"(a), "l"(b));
}
__device__ __forceinline__ void unpack2(ull v, float& lo, float& hi) {
    asm("mov.b64 {%0, %1}, %2;" : "=f"(lo), "=f"(hi) : "l"(v));
}
__device__ __forceinline__ ull pack2(float lo, float hi) {
    ull r; asm("mov.b64 %0, {%1, %2};" : "=l"(r) : "f"(lo), "f"(hi)); return r;
}

// ---------------- K0: init ----------------
__global__ void k_init(int N) {
    int i = blockIdx.x * blockDim.x + threadIdx.x;
    if (i < N) g_deg[i] = 0;
    if (i < G_NUM * 64) { g_sumM[i] = 0.f; g_sqM[i] = 0.f; g_sumS[i] = 0.f; g_sqS[i] = 0.f; }
    if (i < G_NUM) g_cnt[i] = 0.f;
}
__global__ void k_hist(const int* __restrict__ ei, int E) {
    int i = blockIdx.x * blockDim.x + threadIdx.x;
    if (i < E) atomicAdd(&g_deg[ei[E + i]], 1);
}

__global__ __launch_bounds__(1024) void k_scan1(int N) {
    __shared__ int s[1024];
    int tid = threadIdx.x;
    int i = blockIdx.x * 1024 + tid;
    int v = (i < N) ? g_deg[i] : 0;
    s[tid] = v;
    #pragma unroll
    for (int d = 1; d < 1024; d <<= 1) {
        __syncthreads();
        int t = (tid >= d) ? s[tid - d] : 0;
        __syncthreads();
        s[tid] += t;
    }
    __syncthreads();
    if (i < N) g_off[i] = s[tid] - v;
    if (tid == 1023) g_bsum[blockIdx.x] = s[1023];
}

__global__ __launch_bounds__(1024) void k_scan2(int nb) {
    __shared__ int s[1024];
    int tid = threadIdx.x;
    int v = (tid < nb) ? g_bsum[tid] : 0;
    s[tid] = v;
    #pragma unroll
    for (int d = 1; d < 1024; d <<= 1) {
        __syncthreads();
        int t = (tid >= d) ? s[tid - d] : 0;
        __syncthreads();
        s[tid] += t;
    }
    __syncthreads();
    if (tid < nb) g_bsum[tid] = s[tid] - v;
}

__global__ void k_scan3(int N) {
    int i = blockIdx.x * blockDim.x + threadIdx.x;
    if (i >= N) return;
    int o = g_off[i] + g_bsum[i >> 10];
    g_off[i] = o;
    g_cur[i] = o;
}

__global__ void k_fill(const int* __restrict__ ei, int E) {
    int i = blockIdx.x * blockDim.x + threadIdx.x;
    if (i >= E) return;
    int dst = ei[E + i];
    int pos = atomicAdd(&g_cur[dst], 1);
    g_csr[pos] = ei[i];
}

// ---------------- K1: fused GEMM, k-pair FFMA2 (no pack movs in inner loop) ----------------
// acc = {sum over even k, sum over odd k}; a = LDS.64 of x[r][2k:2k+2];
// b from k-interleaved weight smem built by LDG->STS double-buffered pipeline.
#define TROWS 32              // rows per block
#define RPT   4               // rows per warp
#define KCH   8               // k per chunk (4 k-pairs)
#define NCH   16              // 128 / KCH
__global__ __launch_bounds__(256, 3) void k_gemm(
    const float* __restrict__ x,
    const float* __restrict__ Wl, const float* __restrict__ Wr,
    const float* __restrict__ Ws, const float* __restrict__ skip_b, int N)
{
    __shared__ float Xs[TROWS * 128];        // 16 KB
    __shared__ ull   Wp[2][4][192];          // 12 KB (double-buffered k-paired weights)
    int tid = threadIdx.x;
    int lane = tid & 31, w = tid >> 5;
    int rowBase = blockIdx.x * TROWS;

    // ---- load weight chunk 0 into regs ----
    float2 wreg[3];
    #pragma unroll
    for (int t = 0; t < 3; t++) {
        int idx = tid + t * 256;
        int k2 = idx / 192, c = idx - 192 * k2;
        const float* Wm = (c < 64) ? Wl : ((c < 128) ? Wr : Ws);
        int cc = c & 63;
        int kE = 2 * k2;
        wreg[t].x = __ldg(Wm + (size_t)kE * 64 + cc);
        wreg[t].y = __ldg(Wm + (size_t)(kE + 1) * 64 + cc);
    }

    // ---- X tile load (coalesced, row-major, no swizzle needed) ----
    const float4* xg = (const float4*)x;
    for (int i = tid; i < TROWS * 32; i += 256) {
        int r = i >> 5, c4 = i & 31;
        int gr = rowBase + r;
        float4 v = (gr < N) ? __ldg(xg + (size_t)gr * 32 + c4) : make_float4(0.f, 0.f, 0.f, 0.f);
        ((float4*)Xs)[i] = v;
    }

    // ---- store chunk 0 ----
    #pragma unroll
    for (int t = 0; t < 3; t++) {
        int idx = tid + t * 256;
        int k2 = idx / 192, c = idx - 192 * k2;
        Wp[0][k2][c] = pack2(wreg[t].x, wreg[t].y);
    }
    __syncthreads();

    ull acc[RPT][6];
    #pragma unroll
    for (int i = 0; i < RPT; i++)
        #pragma unroll
        for (int j = 0; j < 6; j++) acc[i][j] = 0ULL;

    for (int ch = 0; ch < NCH; ch++) {
        int buf = ch & 1;
        // prefetch next chunk's weights to regs (LDG hidden under compute)
        if (ch + 1 < NCH) {
            #pragma unroll
            for (int t = 0; t < 3; t++) {
                int idx = tid + t * 256;
                int k2 = idx / 192, c = idx - 192 * k2;
                const float* Wm = (c < 64) ? Wl : ((c < 128) ? Wr : Ws);
                int cc = c & 63;
                int kE = (ch + 1) * KCH + 2 * k2;
                wreg[t].x = __ldg(Wm + (size_t)kE * 64 + cc);
                wreg[t].y = __ldg(Wm + (size_t)(kE + 1) * 64 + cc);
            }
        }
        // compute on current buffer
        #pragma unroll
        for (int k2 = 0; k2 < 4; k2++) {
            ull b[6];
            #pragma unroll
            for (int j = 0; j < 6; j++) b[j] = Wp[buf][k2][lane + 32 * j];
            #pragma unroll
            for (int i = 0; i < RPT; i++) {
                int row = w * RPT + i;
                ull a = *(const ull*)&Xs[row * 128 + ch * KCH + 2 * k2];   // broadcast LDS.64
                #pragma unroll
                for (int j = 0; j < 6; j++) fma2(acc[i][j], a, b[j]);
            }
        }
        // stage next chunk into the other buffer
        if (ch + 1 < NCH) {
            int nb2 = buf ^ 1;
            #pragma unroll
            for (int t = 0; t < 3; t++) {
                int idx = tid + t * 256;
                int k2 = idx / 192, c = idx - 192 * k2;
                Wp[nb2][k2][c] = pack2(wreg[t].x, wreg[t].y);
            }
        }
        __syncthreads();
    }

    // ---- epilogue: fold halves, scatter to xl/xr/xs ----
    float sb[2];
    sb[0] = __ldg(skip_b + lane);
    sb[1] = __ldg(skip_b + 32 + lane);
    #pragma unroll
    for (int i = 0; i < RPT; i++) {
        int row = rowBase + w * RPT + i;
        if (row >= N) break;
        #pragma unroll
        for (int j = 0; j < 6; j++) {
            float lo, hi; unpack2(acc[i][j], lo, hi);
            float v = lo + hi;
            int half = j & 1;
            int c = lane + 32 * half;
            if (j < 2)       g_xl[(size_t)row * 64 + c] = v;
            else if (j < 4)  g_xr[(size_t)row * 64 + c] = v;
            else             g_xs[(size_t)row * 64 + c] = v + sb[half];
        }
    }
}

// ---------------- K2: per-dst softmax-aggregate, no-max, 2 edges/warp, float4 ----------------
__global__ __launch_bounds__(256) void k_edge(
    const float* __restrict__ att, const float* __restrict__ conv_bias, int N, int E)
{
    int gw = (blockIdx.x * blockDim.x + threadIdx.x) >> 5;
    if (gw >= N) return;
    int lane = threadIdx.x & 31;
    int half = lane >> 4;            // 0 or 1
    int l = lane & 15;               // float4 slot -> channels 4l..4l+3
    int d = gw;
    unsigned hmask = half ? 0xFFFF0000u : 0x0000FFFFu;

    const float4* xl4 = (const float4*)g_xl;
    float4 xr = __ldg((const float4*)g_xr + (size_t)d * 16 + l);
    float4 at = __ldg((const float4*)att + l);

    float den = 0.f, s0 = 0.f, s1 = 0.f, s2 = 0.f, s3 = 0.f;

    int e0  = g_off[d];
    int end = (d + 1 < N) ? g_off[d + 1] : E;
    int nE  = end - e0;
    int cnt = (nE - half + 1) >> 1;
    if (cnt < 0) cnt = 0;
    int base = e0 + half;

    if (half == 1) {
        float4 v = __ldg(xl4 + (size_t)d * 16 + l);
        float t0 = v.x + xr.x, t1 = v.y + xr.y, t2 = v.z + xr.z, t3 = v.w + xr.w;
        t0 = t0 > 0.f ? t0 : 0.2f * t0;
        t1 = t1 > 0.f ? t1 : 0.2f * t1;
        t2 = t2 > 0.f ? t2 : 0.2f * t2;
        t3 = t3 > 0.f ? t3 : 0.2f * t3;
        float p = fmaf(t0, at.x, fmaf(t1, at.y, fmaf(t2, at.z, t3 * at.w)));
        p += __shfl_xor_sync(hmask, p, 1);
        p += __shfl_xor_sync(hmask, p, 2);
        float ex = __expf(p);
        den += ex;
        s0 = fmaf(v.x, ex, s0);
        s1 = fmaf(v.y, ex, s1);
        s2 = fmaf(v.z, ex, s2);
        s3 = fmaf(v.w, ex, s3);
    } else {
        float p = 0.f;
        p += __shfl_xor_sync(hmask, p, 1);
        p += __shfl_xor_sync(hmask, p, 2);
    }

    #pragma unroll 4
    for (int it = 0; it < cnt; it++) {
        int src = __ldg(&g_csr[base + 2 * it]);
        float4 v = __ldg(xl4 + (size_t)src * 16 + l);
        float t0 = v.x + xr.x, t1 = v.y + xr.y, t2 = v.z + xr.z, t3 = v.w + xr.w;
        t0 = t0 > 0.f ? t0 : 0.2f * t0;
        t1 = t1 > 0.f ? t1 : 0.2f * t1;
        t2 = t2 > 0.f ? t2 : 0.2f * t2;
        t3 = t3 > 0.f ? t3 : 0.2f * t3;
        float p = fmaf(t0, at.x, fmaf(t1, at.y, fmaf(t2, at.z, t3 * at.w)));
        p += __shfl_xor_sync(hmask, p, 1);
        p += __shfl_xor_sync(hmask, p, 2);
        float ex = __expf(p);
        den += ex;
        s0 = fmaf(v.x, ex, s0);
        s1 = fmaf(v.y, ex, s1);
        s2 = fmaf(v.z, ex, s2);
        s3 = fmaf(v.w, ex, s3);
    }

    __syncwarp();
    den += __shfl_xor_sync(0xffffffffu, den, 16);
    s0  += __shfl_xor_sync(0xffffffffu, s0, 16);
    s1  += __shfl_xor_sync(0xffffffffu, s1, 16);
    s2  += __shfl_xor_sync(0xffffffffu, s2, 16);
    s3  += __shfl_xor_sync(0xffffffffu, s3, 16);

    if (half == 0) {
        float inv = 1.f / den;
        float4 cb = __ldg((const float4*)conv_bias + l);
        float4 o;
        o.x = fmaf(s0, inv, cb.x);
        o.y = fmaf(s1, inv, cb.y);
        o.z = fmaf(s2, inv, cb.z);
        o.w = fmaf(s3, inv, cb.w);
        ((float4*)g_out)[(size_t)d * 16 + l] = o;
    }
}

// ---------------- K3: per-graph sums + sumsq (single pass) ----------------
__global__ __launch_bounds__(256) void k_stats(const int* __restrict__ batch, int N)
{
    int gid = blockIdx.x * blockDim.x + threadIdx.x;
    int ch = gid & 63;
    int slot = gid >> 6;
    int n0 = slot * 32;
    if (n0 >= N) return;
    int n1 = min(n0 + 32, N);

    int gfirst = batch[n0], glast = batch[n1 - 1];
    if (gfirst == glast) {
        float aM = 0.f, qM = 0.f, aS = 0.f, qS = 0.f;
        #pragma unroll 4
        for (int n = n0; n < n1; n++) {
            float vm = g_out[(size_t)n * 64 + ch];
            float vs = g_xs [(size_t)n * 64 + ch];
            aM += vm; qM = fmaf(vm, vm, qM);
            aS += vs; qS = fmaf(vs, vs, qS);
        }
        atomicAdd(&g_sumM[gfirst * 64 + ch], aM);
        atomicAdd(&g_sqM [gfirst * 64 + ch], qM);
        atomicAdd(&g_sumS[gfirst * 64 + ch], aS);
        atomicAdd(&g_sqS [gfirst * 64 + ch], qS);
        if (ch == 0) atomicAdd(&g_cnt[gfirst], (float)(n1 - n0));
        return;
    }

    float aM = 0.f, qM = 0.f, aS = 0.f, qS = 0.f, ac = 0.f;
    int curg = gfirst;
    for (int n = n0; n < n1; n++) {
        int g = batch[n];
        if (g != curg) {
            atomicAdd(&g_sumM[curg * 64 + ch], aM);
            atomicAdd(&g_sqM [curg * 64 + ch], qM);
            atomicAdd(&g_sumS[curg * 64 + ch], aS);
            atomicAdd(&g_sqS [curg * 64 + ch], qS);
            if (ch == 0) atomicAdd(&g_cnt[curg], ac);
            aM = qM = aS = qS = ac = 0.f; curg = g;
        }
        float vm = g_out[(size_t)n * 64 + ch];
        float vs = g_xs [(size_t)n * 64 + ch];
        aM += vm; qM = fmaf(vm, vm, qM);
        aS += vs; qS = fmaf(vs, vs, qS);
        ac += 1.f;
    }
    atomicAdd(&g_sumM[curg * 64 + ch], aM);
    atomicAdd(&g_sqM [curg * 64 + ch], qM);
    atomicAdd(&g_sumS[curg * 64 + ch], aS);
    atomicAdd(&g_sqS [curg * 64 + ch], qS);
    if (ch == 0) atomicAdd(&g_cnt[curg], ac);
}

// ---------------- K3b: precompute per-(graph,channel) affine coeffs ----------------
__global__ void k_prec(
    const float* __restrict__ bn_w, const float* __restrict__ bn_b, const float* __restrict__ bn_ms,
    const float* __restrict__ sn_w, const float* __restrict__ sn_b, const float* __restrict__ sn_ms)
{
    int i = blockIdx.x * blockDim.x + threadIdx.x;
    if (i >= G_NUM * 64) return;
    int g = i >> 6, ch = i & 63;
    float cntv = fmaxf(g_cnt[g], 1.f);
    float rinv = 1.f / cntv;
    float msM = bn_ms[ch], msS = sn_ms[ch];

    float meanM = g_sumM[i] * rinv;
    float eqM   = g_sqM [i] * rinv;
    float varM  = fmaxf(eqM - meanM * meanM * msM * (2.f - msM), 0.f);
    float meanS = g_sumS[i] * rinv;
    float eqS   = g_sqS [i] * rinv;
    float varS  = fmaxf(eqS - meanS * meanS * msS * (2.f - msS), 0.f);

    float cM = bn_w[ch] * rsqrtf(varM + 1e-5f);
    float cS = sn_w[ch] * rsqrtf(varS + 1e-5f);
    float C  = bn_b[ch] + sn_b[ch] - cM * meanM * msM - cS * meanS * msS;
    g_sumM[i] = cM;
    g_sumS[i] = cS;
    g_sqM [i] = C;
}

// ---------------- K4: y = cM*vm + cS*vs + C, then ELU (float4) ----------------
__global__ __launch_bounds__(256) void k_final(
    const int* __restrict__ batch, float* __restrict__ out, int N)
{
    int i = blockIdx.x * blockDim.x + threadIdx.x;
    if (i >= N * 16) return;
    int n = i >> 4, q = i & 15;
    int g = batch[n];

    float4 cM = ((const float4*)g_sumM)[g * 16 + q];
    float4 cS = ((const float4*)g_sumS)[g * 16 + q];
    float4 C  = ((const float4*)g_sqM )[g * 16 + q];
    float4 vm = ((const float4*)g_out)[i];
    float4 vs = ((const float4*)g_xs)[i];

    float4 res;
    float y;
    y = fmaf(cM.x, vm.x, fmaf(cS.x, vs.x, C.x)); res.x = (y > 0.f) ? y : (__expf(y) - 1.f);
    y = fmaf(cM.y, vm.y, fmaf(cS.y, vs.y, C.y)); res.y = (y > 0.f) ? y : (__expf(y) - 1.f);
    y = fmaf(cM.z, vm.z, fmaf(cS.z, vs.z, C.z)); res.z = (y > 0.f) ? y : (__expf(y) - 1.f);
    y = fmaf(cM.w, vm.w, fmaf(cS.w, vs.w, C.w)); res.w = (y > 0.f) ? y : (__expf(y) - 1.f);
    ((float4*)out)[i] = res;
}

// ---------------- launch ----------------
extern "C" void kernel_launch(void* const* d_in, const int* in_sizes, int n_in,
                              void* d_out, int out_size)
{
    const float* x         = (const float*)d_in[0];
    const int*   ei        = (const int*)d_in[1];
    const int*   batch     = (const int*)d_in[2];
    const float* Wl        = (const float*)d_in[3];
    const float* Wr        = (const float*)d_in[4];
    const float* att       = (const float*)d_in[5];
    const float* conv_bias = (const float*)d_in[6];
    const float* skip_W    = (const float*)d_in[7];
    const float* skip_b    = (const float*)d_in[8];
    const float* bn_w      = (const float*)d_in[9];
    const float* bn_b      = (const float*)d_in[10];
    const float* bn_ms     = (const float*)d_in[11];
    const float* sn_w      = (const float*)d_in[12];
    const float* sn_b      = (const float*)d_in[13];
    const float* sn_ms     = (const float*)d_in[14];
    float*       out       = (float*)d_out;

    int N  = in_sizes[0] / 128;
    int E  = in_sizes[1] / 2;
    int nb = (N + 1023) / 1024;

    k_init <<<(N + 255) / 256, 256>>>(N);                    // 1
    k_hist <<<(E + 255) / 256, 256>>>(ei, E);                // 2
    k_scan1<<<nb, 1024>>>(N);                                // 3
    k_gemm <<<(N + TROWS - 1) / TROWS, 256>>>(x, Wl, Wr, skip_W, skip_b, N);  // 4 (profiled slot)
    k_scan2<<<1, 1024>>>(nb);                                // 5
    k_scan3<<<(N + 255) / 256, 256>>>(N);                    // 6
    k_fill <<<(E + 255) / 256, 256>>>(ei, E);                // 7

    {   // 8: edge, 1 warp per node
        long long threads = (long long)N * 32;
        k_edge<<<(unsigned)((threads + 255) / 256), 256>>>(att, conv_bias, N, E);
    }
    {   // 9: stats
        int slots = (N + 31) / 32;
        long long threads = (long long)slots * 64;
        k_stats<<<(unsigned)((threads + 255) / 256), 256>>>(batch, N);
    }
    k_prec<<<(G_NUM * 64 + 255) / 256, 256>>>(bn_w, bn_b, bn_ms, sn_w, sn_b, sn_ms);  // 10
    {   // 11: final
        long long total = (long long)N * 16;
        k_final<<<(unsigned)((total + 255) / 256), 256>>>(batch, out, N);
    }
}

// round 10
// speedup vs baseline: 1.2057x; 1.2057x over previous
#include <cuda_runtime.h>
#include <cuda_bf16.h>
#include <cstdint>
#include <math.h>

#define N_MAX   100000
#define E_MAX   1600000
#define G_NUM   64

typedef unsigned long long ull;

// ---------------- scratch (device globals; no allocation) ----------------
__device__ __align__(16) float g_xl[N_MAX * 64];
__device__ __align__(16) float g_xr[N_MAX * 64];
__device__ __align__(16) float g_xs[N_MAX * 64];
__device__ __align__(16) float g_out[N_MAX * 64];
__device__ int   g_deg[N_MAX];
__device__ int   g_off[N_MAX];
__device__ int   g_cur[N_MAX];
__device__ int   g_csr[E_MAX];
__device__ int   g_bsum[1024];
__device__ float g_sumM[G_NUM * 64];   // later reused: cM
__device__ float g_sqM [G_NUM * 64];   // later reused: C
__device__ float g_sumS[G_NUM * 64];   // later reused: cS
__device__ float g_sqS [G_NUM * 64];
__device__ float g_cnt [G_NUM];

// ---------------- f32x2 helpers ----------------
__device__ __forceinline__ ull pack_dup(float a) {
    ull r; asm("mov.b64 %0, {%1, %1};" : "=l"(r) : "f"(a)); return r;
}
__device__ __forceinline__ void fma2(ull& d, ull a, ull b) {
    asm("fma.rn.f32x2 %0, %1, %2, %0;" : "+l"(d) : "l"(a), "l"(b));
}
__device__ __forceinline__ void unpack2(ull v, float& lo, float& hi) {
    asm("mov.b64 {%0, %1}, %2;" : "=f"(lo), "=f"(hi) : "l"(v));
}

// ---------------- K0: init ----------------
__global__ void k_init(int N) {
    int i = blockIdx.x * blockDim.x + threadIdx.x;
    if (i < N) g_deg[i] = 0;
    if (i < G_NUM * 64) { g_sumM[i] = 0.f; g_sqM[i] = 0.f; g_sumS[i] = 0.f; g_sqS[i] = 0.f; }
    if (i < G_NUM) g_cnt[i] = 0.f;
}
__global__ void k_hist(const int* __restrict__ ei, int E) {
    int i = blockIdx.x * blockDim.x + threadIdx.x;
    if (i < E) atomicAdd(&g_deg[ei[E + i]], 1);
}

__global__ __launch_bounds__(1024) void k_scan1(int N) {
    __shared__ int s[1024];
    int tid = threadIdx.x;
    int i = blockIdx.x * 1024 + tid;
    int v = (i < N) ? g_deg[i] : 0;
    s[tid] = v;
    #pragma unroll
    for (int d = 1; d < 1024; d <<= 1) {
        __syncthreads();
        int t = (tid >= d) ? s[tid - d] : 0;
        __syncthreads();
        s[tid] += t;
    }
    __syncthreads();
    if (i < N) g_off[i] = s[tid] - v;
    if (tid == 1023) g_bsum[blockIdx.x] = s[1023];
}

__global__ __launch_bounds__(1024) void k_scan2(int nb) {
    __shared__ int s[1024];
    int tid = threadIdx.x;
    int v = (tid < nb) ? g_bsum[tid] : 0;
    s[tid] = v;
    #pragma unroll
    for (int d = 1; d < 1024; d <<= 1) {
        __syncthreads();
        int t = (tid >= d) ? s[tid - d] : 0;
        __syncthreads();
        s[tid] += t;
    }
    __syncthreads();
    if (tid < nb) g_bsum[tid] = s[tid] - v;
}

__global__ void k_scan3(int N) {
    int i = blockIdx.x * blockDim.x + threadIdx.x;
    if (i >= N) return;
    int o = g_off[i] + g_bsum[i >> 10];
    g_off[i] = o;
    g_cur[i] = o;
}

__global__ void k_fill(const int* __restrict__ ei, int E) {
    int i = blockIdx.x * blockDim.x + threadIdx.x;
    if (i >= E) return;
    int dst = ei[E + i];
    int pos = atomicAdd(&g_cur[dst], 1);
    g_csr[pos] = ei[i];
}

// ---------------- K1: fused GEMM, cp.async chunks + register-pipelined LDS (R8 version) ----
#define KCH 16                // k per chunk
#define NCH (128 / KCH)       // 8 chunks
__global__ __launch_bounds__(256, 2) void k_gemm(
    const float* __restrict__ x,
    const float* __restrict__ Wl, const float* __restrict__ Wr,
    const float* __restrict__ Ws, const float* __restrict__ skip_b, int N)
{
    __shared__ float Xs[64 * 128];            // 32 KB
    __shared__ ull   Wsm[2][KCH][96];         // 24 KB (double-buffered weight chunk)
    int tid = threadIdx.x;
    int rowBase = blockIdx.x * 64;

    const ull* wsrc0 = (const ull*)Wl;
    const ull* wsrc1 = (const ull*)Wr;
    const ull* wsrc2 = (const ull*)Ws;

    {
        for (int s = tid; s < KCH * 48; s += 256) {
            int mat = s / 256;
            int rem = s & 255;
            int k = rem >> 4;
            int f4 = rem & 15;
            const ull* src = (mat == 0 ? wsrc0 : mat == 1 ? wsrc1 : wsrc2)
                             + (size_t)k * 32 + f4 * 2;
            unsigned int da = (unsigned int)__cvta_generic_to_shared(&Wsm[0][k][mat * 32 + f4 * 2]);
            asm volatile("cp.async.cg.shared.global [%0], [%1], 16;" :: "r"(da), "l"(src));
        }
        asm volatile("cp.async.commit_group;");
    }

    const float4* xg = (const float4*)x;
    for (int i = tid; i < 64 * 32; i += 256) {
        int r = i >> 5, c4 = i & 31;
        int gr = rowBase + r;
        float4 v = (gr < N) ? __ldg(xg + (size_t)gr * 32 + c4) : make_float4(0.f, 0.f, 0.f, 0.f);
        ((float4*)Xs)[i] = v;
    }

    int tr = tid >> 5, tc = tid & 31;
    ull acc[8][3];
    #pragma unroll
    for (int i = 0; i < 8; i++)
        #pragma unroll
        for (int j = 0; j < 3; j++) acc[i][j] = 0ULL;

    for (int c = 0; c < NCH; c++) {
        int buf = c & 1;
        if (c + 1 < NCH) {
            int nb2 = buf ^ 1;
            for (int s = tid; s < KCH * 48; s += 256) {
                int mat = s / 256;
                int rem = s & 255;
                int k = rem >> 4;
                int f4 = rem & 15;
                const ull* src = (mat == 0 ? wsrc0 : mat == 1 ? wsrc1 : wsrc2)
                                 + (size_t)((c + 1) * KCH + k) * 32 + f4 * 2;
                unsigned int da = (unsigned int)__cvta_generic_to_shared(&Wsm[nb2][k][mat * 32 + f4 * 2]);
                asm volatile("cp.async.cg.shared.global [%0], [%1], 16;" :: "r"(da), "l"(src));
            }
            asm volatile("cp.async.commit_group;");
            asm volatile("cp.async.wait_group 1;");
        } else {
            asm volatile("cp.async.wait_group 0;");
        }
        __syncthreads();

        ull wA[12];
        #pragma unroll
        for (int kk = 0; kk < 4; kk++) {
            wA[kk]     = Wsm[buf][kk][tc];
            wA[4 + kk] = Wsm[buf][kk][32 + tc];
            wA[8 + kk] = Wsm[buf][kk][64 + tc];
        }
        #pragma unroll
        for (int k0 = 0; k0 < KCH; k0 += 4) {
            ull wB[12];
            if (k0 + 4 < KCH) {
                #pragma unroll
                for (int kk = 0; kk < 4; kk++) {
                    wB[kk]     = Wsm[buf][k0 + 4 + kk][tc];
                    wB[4 + kk] = Wsm[buf][k0 + 4 + kk][32 + tc];
                    wB[8 + kk] = Wsm[buf][k0 + 4 + kk][64 + tc];
                }
            }
            #pragma unroll
            for (int grp = 0; grp < 2; grp++) {
                float4 av[4];
                #pragma unroll
                for (int i = 0; i < 4; i++)
                    av[i] = *(const float4*)&Xs[(tr * 8 + grp * 4 + i) * 128 + c * KCH + k0];
                #pragma unroll
                for (int kk = 0; kk < 4; kk++) {
                    #pragma unroll
                    for (int i = 0; i < 4; i++) {
                        float a = (kk == 0) ? av[i].x : (kk == 1) ? av[i].y : (kk == 2) ? av[i].z : av[i].w;
                        ull ad = pack_dup(a);
                        int row = grp * 4 + i;
                        fma2(acc[row][0], ad, wA[kk]);
                        fma2(acc[row][1], ad, wA[4 + kk]);
                        fma2(acc[row][2], ad, wA[8 + kk]);
                    }
                }
            }
            if (k0 + 4 < KCH) {
                #pragma unroll
                for (int j = 0; j < 12; j++) wA[j] = wB[j];
            }
        }
        __syncthreads();
    }

    float sb0 = __ldg(skip_b + 2 * tc), sb1 = __ldg(skip_b + 2 * tc + 1);
    #pragma unroll
    for (int i = 0; i < 8; i++) {
        int gr = rowBase + tr * 8 + i;
        if (gr >= N) break;
        ((ull*)g_xl)[(size_t)gr * 32 + tc] = acc[i][0];
        ((ull*)g_xr)[(size_t)gr * 32 + tc] = acc[i][1];
        float lo, hi; unpack2(acc[i][2], lo, hi);
        float2 o; o.x = lo + sb0; o.y = hi + sb1;
        ((float2*)g_xs)[(size_t)gr * 32 + tc] = o;
    }
}

// ---------------- K2: per-dst softmax-aggregate, no-max, 2 edges/warp, float4 ----------------
__global__ __launch_bounds__(256) void k_edge(
    const float* __restrict__ att, const float* __restrict__ conv_bias, int N, int E)
{
    int gw = (blockIdx.x * blockDim.x + threadIdx.x) >> 5;
    if (gw >= N) return;
    int lane = threadIdx.x & 31;
    int half = lane >> 4;
    int l = lane & 15;
    int d = gw;
    unsigned hmask = half ? 0xFFFF0000u : 0x0000FFFFu;

    const float4* xl4 = (const float4*)g_xl;
    float4 xr = __ldg((const float4*)g_xr + (size_t)d * 16 + l);
    float4 at = __ldg((const float4*)att + l);

    float den = 0.f, s0 = 0.f, s1 = 0.f, s2 = 0.f, s3 = 0.f;

    int e0  = g_off[d];
    int end = (d + 1 < N) ? g_off[d + 1] : E;
    int nE  = end - e0;
    int cnt = (nE - half + 1) >> 1;
    if (cnt < 0) cnt = 0;
    int base = e0 + half;

    if (half == 1) {
        float4 v = __ldg(xl4 + (size_t)d * 16 + l);
        float t0 = v.x + xr.x, t1 = v.y + xr.y, t2 = v.z + xr.z, t3 = v.w + xr.w;
        t0 = t0 > 0.f ? t0 : 0.2f * t0;
        t1 = t1 > 0.f ? t1 : 0.2f * t1;
        t2 = t2 > 0.f ? t2 : 0.2f * t2;
        t3 = t3 > 0.f ? t3 : 0.2f * t3;
        float p = fmaf(t0, at.x, fmaf(t1, at.y, fmaf(t2, at.z, t3 * at.w)));
        p += __shfl_xor_sync(hmask, p, 1);
        p += __shfl_xor_sync(hmask, p, 2);
        float ex = __expf(p);
        den += ex;
        s0 = fmaf(v.x, ex, s0);
        s1 = fmaf(v.y, ex, s1);
        s2 = fmaf(v.z, ex, s2);
        s3 = fmaf(v.w, ex, s3);
    } else {
        float p = 0.f;
        p += __shfl_xor_sync(hmask, p, 1);
        p += __shfl_xor_sync(hmask, p, 2);
    }

    #pragma unroll 4
    for (int it = 0; it < cnt; it++) {
        int src = __ldg(&g_csr[base + 2 * it]);
        float4 v = __ldg(xl4 + (size_t)src * 16 + l);
        float t0 = v.x + xr.x, t1 = v.y + xr.y, t2 = v.z + xr.z, t3 = v.w + xr.w;
        t0 = t0 > 0.f ? t0 : 0.2f * t0;
        t1 = t1 > 0.f ? t1 : 0.2f * t1;
        t2 = t2 > 0.f ? t2 : 0.2f * t2;
        t3 = t3 > 0.f ? t3 : 0.2f * t3;
        float p = fmaf(t0, at.x, fmaf(t1, at.y, fmaf(t2, at.z, t3 * at.w)));
        p += __shfl_xor_sync(hmask, p, 1);
        p += __shfl_xor_sync(hmask, p, 2);
        float ex = __expf(p);
        den += ex;
        s0 = fmaf(v.x, ex, s0);
        s1 = fmaf(v.y, ex, s1);
        s2 = fmaf(v.z, ex, s2);
        s3 = fmaf(v.w, ex, s3);
    }

    __syncwarp();
    den += __shfl_xor_sync(0xffffffffu, den, 16);
    s0  += __shfl_xor_sync(0xffffffffu, s0, 16);
    s1  += __shfl_xor_sync(0xffffffffu, s1, 16);
    s2  += __shfl_xor_sync(0xffffffffu, s2, 16);
    s3  += __shfl_xor_sync(0xffffffffu, s3, 16);

    if (half == 0) {
        float inv = 1.f / den;
        float4 cb = __ldg((const float4*)conv_bias + l);
        float4 o;
        o.x = fmaf(s0, inv, cb.x);
        o.y = fmaf(s1, inv, cb.y);
        o.z = fmaf(s2, inv, cb.z);
        o.w = fmaf(s3, inv, cb.w);
        ((float4*)g_out)[(size_t)d * 16 + l] = o;
    }
}

// ---------------- K3: per-graph sums + sumsq (single pass) ----------------
__global__ __launch_bounds__(256) void k_stats(const int* __restrict__ batch, int N)
{
    int gid = blockIdx.x * blockDim.x + threadIdx.x;
    int ch = gid & 63;
    int slot = gid >> 6;
    int n0 = slot * 32;
    if (n0 >= N) return;
    int n1 = min(n0 + 32, N);

    int gfirst = batch[n0], glast = batch[n1 - 1];
    if (gfirst == glast) {
        float aM = 0.f, qM = 0.f, aS = 0.f, qS = 0.f;
        #pragma unroll 4
        for (int n = n0; n < n1; n++) {
            float vm = g_out[(size_t)n * 64 + ch];
            float vs = g_xs [(size_t)n * 64 + ch];
            aM += vm; qM = fmaf(vm, vm, qM);
            aS += vs; qS = fmaf(vs, vs, qS);
        }
        atomicAdd(&g_sumM[gfirst * 64 + ch], aM);
        atomicAdd(&g_sqM [gfirst * 64 + ch], qM);
        atomicAdd(&g_sumS[gfirst * 64 + ch], aS);
        atomicAdd(&g_sqS [gfirst * 64 + ch], qS);
        if (ch == 0) atomicAdd(&g_cnt[gfirst], (float)(n1 - n0));
        return;
    }

    float aM = 0.f, qM = 0.f, aS = 0.f, qS = 0.f, ac = 0.f;
    int curg = gfirst;
    for (int n = n0; n < n1; n++) {
        int g = batch[n];
        if (g != curg) {
            atomicAdd(&g_sumM[curg * 64 + ch], aM);
            atomicAdd(&g_sqM [curg * 64 + ch], qM);
            atomicAdd(&g_sumS[curg * 64 + ch], aS);
            atomicAdd(&g_sqS [curg * 64 + ch], qS);
            if (ch == 0) atomicAdd(&g_cnt[curg], ac);
            aM = qM = aS = qS = ac = 0.f; curg = g;
        }
        float vm = g_out[(size_t)n * 64 + ch];
        float vs = g_xs [(size_t)n * 64 + ch];
        aM += vm; qM = fmaf(vm, vm, qM);
        aS += vs; qS = fmaf(vs, vs, qS);
        ac += 1.f;
    }
    atomicAdd(&g_sumM[curg * 64 + ch], aM);
    atomicAdd(&g_sqM [curg * 64 + ch], qM);
    atomicAdd(&g_sumS[curg * 64 + ch], aS);
    atomicAdd(&g_sqS [curg * 64 + ch], qS);
    if (ch == 0) atomicAdd(&g_cnt[curg], ac);
}

// ---------------- K3b: precompute per-(graph,channel) affine coeffs ----------------
__global__ void k_prec(
    const float* __restrict__ bn_w, const float* __restrict__ bn_b, const float* __restrict__ bn_ms,
    const float* __restrict__ sn_w, const float* __restrict__ sn_b, const float* __restrict__ sn_ms)
{
    int i = blockIdx.x * blockDim.x + threadIdx.x;
    if (i >= G_NUM * 64) return;
    int g = i >> 6, ch = i & 63;
    float cntv = fmaxf(g_cnt[g], 1.f);
    float rinv = 1.f / cntv;
    float msM = bn_ms[ch], msS = sn_ms[ch];

    float meanM = g_sumM[i] * rinv;
    float eqM   = g_sqM [i] * rinv;
    float varM  = fmaxf(eqM - meanM * meanM * msM * (2.f - msM), 0.f);
    float meanS = g_sumS[i] * rinv;
    float eqS   = g_sqS [i] * rinv;
    float varS  = fmaxf(eqS - meanS * meanS * msS * (2.f - msS), 0.f);

    float cM = bn_w[ch] * rsqrtf(varM + 1e-5f);
    float cS = sn_w[ch] * rsqrtf(varS + 1e-5f);
    float C  = bn_b[ch] + sn_b[ch] - cM * meanM * msM - cS * meanS * msS;
    g_sumM[i] = cM;
    g_sumS[i] = cS;
    g_sqM [i] = C;
}

// ---------------- K4: y = cM*vm + cS*vs + C, then ELU (float4) ----------------
__global__ __launch_bounds__(256) void k_final(
    const int* __restrict__ batch, float* __restrict__ out, int N)
{
    int i = blockIdx.x * blockDim.x + threadIdx.x;
    if (i >= N * 16) return;
    int n = i >> 4, q = i & 15;
    int g = batch[n];

    float4 cM = ((const float4*)g_sumM)[g * 16 + q];
    float4 cS = ((const float4*)g_sumS)[g * 16 + q];
    float4 C  = ((const float4*)g_sqM )[g * 16 + q];
    float4 vm = ((const float4*)g_out)[i];
    float4 vs = ((const float4*)g_xs)[i];

    float4 res;
    float y;
    y = fmaf(cM.x, vm.x, fmaf(cS.x, vs.x, C.x)); res.x = (y > 0.f) ? y : (__expf(y) - 1.f);
    y = fmaf(cM.y, vm.y, fmaf(cS.y, vs.y, C.y)); res.y = (y > 0.f) ? y : (__expf(y) - 1.f);
    y = fmaf(cM.z, vm.z, fmaf(cS.z, vs.z, C.z)); res.z = (y > 0.f) ? y : (__expf(y) - 1.f);
    y = fmaf(cM.w, vm.w, fmaf(cS.w, vs.w, C.w)); res.w = (y > 0.f) ? y : (__expf(y) - 1.f);
    ((float4*)out)[i] = res;
}

// ---------------- launch (fork-join: CSR build overlaps GEMM) ----------------
extern "C" void kernel_launch(void* const* d_in, const int* in_sizes, int n_in,
                              void* d_out, int out_size)
{
    const float* x         = (const float*)d_in[0];
    const int*   ei        = (const int*)d_in[1];
    const int*   batch     = (const int*)d_in[2];
    const float* Wl        = (const float*)d_in[3];
    const float* Wr        = (const float*)d_in[4];
    const float* att       = (const float*)d_in[5];
    const float* conv_bias = (const float*)d_in[6];
    const float* skip_W    = (const float*)d_in[7];
    const float* skip_b    = (const float*)d_in[8];
    const float* bn_w      = (const float*)d_in[9];
    const float* bn_b      = (const float*)d_in[10];
    const float* bn_ms     = (const float*)d_in[11];
    const float* sn_w      = (const float*)d_in[12];
    const float* sn_b      = (const float*)d_in[13];
    const float* sn_ms     = (const float*)d_in[14];
    float*       out       = (float*)d_out;

    int N  = in_sizes[0] / 128;
    int E  = in_sizes[1] / 2;
    int nb = (N + 1023) / 1024;

    static cudaStream_t s1 = nullptr;
    static cudaEvent_t evFork = nullptr, evJoin = nullptr;
    if (s1 == nullptr) {
        cudaStreamCreateWithFlags(&s1, cudaStreamNonBlocking);
        cudaEventCreateWithFlags(&evFork, cudaEventDisableTiming);
        cudaEventCreateWithFlags(&evJoin, cudaEventDisableTiming);
    }

    // fork: CSR build chain on s1, GEMM on the main (capture) stream
    cudaEventRecord(evFork, 0);
    cudaStreamWaitEvent(s1, evFork, 0);

    k_init <<<(N + 255) / 256, 256, 0, s1>>>(N);
    k_hist <<<(E + 255) / 256, 256, 0, s1>>>(ei, E);
    k_scan1<<<nb, 1024, 0, s1>>>(N);
    k_scan2<<<1, 1024, 0, s1>>>(nb);
    k_scan3<<<(N + 255) / 256, 256, 0, s1>>>(N);
    k_fill <<<(E + 255) / 256, 256, 0, s1>>>(ei, E);
    cudaEventRecord(evJoin, s1);

    k_gemm <<<(N + 63) / 64, 256>>>(x, Wl, Wr, skip_W, skip_b, N);

    // join: edge needs both GEMM output and CSR
    cudaStreamWaitEvent(0, evJoin, 0);

    {   // edge: 1 warp per node
        long long threads = (long long)N * 32;
        k_edge<<<(unsigned)((threads + 255) / 256), 256>>>(att, conv_bias, N, E);
    }
    {   // stats
        int slots = (N + 31) / 32;
        long long threads = (long long)slots * 64;
        k_stats<<<(unsigned)((threads + 255) / 256), 256>>>(batch, N);
    }
    k_prec<<<(G_NUM * 64 + 255) / 256, 256>>>(bn_w, bn_b, bn_ms, sn_w, sn_b, sn_ms);
    {   // final
        long long total = (long long)N * 16;
        k_final<<<(unsigned)((total + 255) / 256), 256>>>(batch, out, N);
    }
}

// round 11
// speedup vs baseline: 1.2429x; 1.0308x over previous
#include <cuda_runtime.h>
#include <cuda_bf16.h>
#include <cstdint>
#include <math.h>

#define N_MAX   100000
#define E_MAX   1600000
#define G_NUM   64

typedef unsigned long long ull;

// ---------------- scratch (device globals; no allocation) ----------------
__device__ __align__(16) float g_xl[N_MAX * 64];
__device__ __align__(16) float g_xr[N_MAX * 64];
__device__ __align__(16) float g_xs[N_MAX * 64];
__device__ __align__(16) float g_out[N_MAX * 64];
__device__ int   g_deg[N_MAX];
__device__ int   g_off[N_MAX];
__device__ int   g_cur[N_MAX];
__device__ int   g_csr[E_MAX];
__device__ int   g_bsum[1024];
__device__ float g_sumM[G_NUM * 64];   // later reused: cM
__device__ float g_sqM [G_NUM * 64];   // later reused: C
__device__ float g_sumS[G_NUM * 64];   // later reused: cS
__device__ float g_sqS [G_NUM * 64];
__device__ float g_cnt [G_NUM];

// ---------------- f32x2 helpers ----------------
__device__ __forceinline__ ull pack_dup(float a) {
    ull r; asm("mov.b64 %0, {%1, %1};" : "=l"(r) : "f"(a)); return r;
}
__device__ __forceinline__ void fma2(ull& d, ull a, ull b) {
    asm("fma.rn.f32x2 %0, %1, %2, %0;" : "+l"(d) : "l"(a), "l"(b));
}
__device__ __forceinline__ void unpack2(ull v, float& lo, float& hi) {
    asm("mov.b64 {%0, %1}, %2;" : "=f"(lo), "=f"(hi) : "l"(v));
}

// ---------------- K0: init ----------------
__global__ void k_init(int N) {
    int i = blockIdx.x * blockDim.x + threadIdx.x;
    if (i < N) g_deg[i] = 0;
    if (i < G_NUM * 64) { g_sumM[i] = 0.f; g_sqM[i] = 0.f; g_sumS[i] = 0.f; g_sqS[i] = 0.f; }
    if (i < G_NUM) g_cnt[i] = 0.f;
}
__global__ void k_hist(const int* __restrict__ ei, int E) {
    int i = blockIdx.x * blockDim.x + threadIdx.x;
    if (i < E) atomicAdd(&g_deg[ei[E + i]], 1);
}

__global__ __launch_bounds__(1024) void k_scan1(int N) {
    __shared__ int s[1024];
    int tid = threadIdx.x;
    int i = blockIdx.x * 1024 + tid;
    int v = (i < N) ? g_deg[i] : 0;
    s[tid] = v;
    #pragma unroll
    for (int d = 1; d < 1024; d <<= 1) {
        __syncthreads();
        int t = (tid >= d) ? s[tid - d] : 0;
        __syncthreads();
        s[tid] += t;
    }
    __syncthreads();
    if (i < N) g_off[i] = s[tid] - v;
    if (tid == 1023) g_bsum[blockIdx.x] = s[1023];
}

__global__ __launch_bounds__(1024) void k_scan2(int nb) {
    __shared__ int s[1024];
    int tid = threadIdx.x;
    int v = (tid < nb) ? g_bsum[tid] : 0;
    s[tid] = v;
    #pragma unroll
    for (int d = 1; d < 1024; d <<= 1) {
        __syncthreads();
        int t = (tid >= d) ? s[tid - d] : 0;
        __syncthreads();
        s[tid] += t;
    }
    __syncthreads();
    if (tid < nb) g_bsum[tid] = s[tid] - v;
}

__global__ void k_scan3(int N) {
    int i = blockIdx.x * blockDim.x + threadIdx.x;
    if (i >= N) return;
    int o = g_off[i] + g_bsum[i >> 10];
    g_off[i] = o;
    g_cur[i] = o;
}

__global__ void k_fill(const int* __restrict__ ei, int E) {
    int i = blockIdx.x * blockDim.x + threadIdx.x;
    if (i >= E) return;
    int dst = ei[E + i];
    int pos = atomicAdd(&g_cur[dst], 1);
    g_csr[pos] = ei[i];
}

// ---------------- K1: fused GEMM, cp.async chunks + register-pipelined LDS ----------------
#define KCH 32                // k per chunk
#define NCH (128 / KCH)       // 4 chunks
__global__ __launch_bounds__(256, 2) void k_gemm(
    const float* __restrict__ x,
    const float* __restrict__ Wl, const float* __restrict__ Wr,
    const float* __restrict__ Ws, const float* __restrict__ skip_b, int N)
{
    __shared__ float Xs[64 * 128];            // 32 KB
    __shared__ ull   Wsm[2][KCH][96];         // 48 KB (double-buffered weight chunk)
    int tid = threadIdx.x;
    int rowBase = blockIdx.x * 64;

    const ull* wsrc0 = (const ull*)Wl;
    const ull* wsrc1 = (const ull*)Wr;
    const ull* wsrc2 = (const ull*)Ws;

    {
        for (int s = tid; s < KCH * 48; s += 256) {
            int mat = s / 512;                 // 512 f4 per matrix (32k x 16f4)
            int rem = s % 512;
            int k = rem >> 4;
            int f4 = rem & 15;
            const ull* src = (mat == 0 ? wsrc0 : mat == 1 ? wsrc1 : wsrc2)
                             + (size_t)k * 32 + f4 * 2;
            unsigned int da = (unsigned int)__cvta_generic_to_shared(&Wsm[0][k][mat * 32 + f4 * 2]);
            asm volatile("cp.async.cg.shared.global [%0], [%1], 16;" :: "r"(da), "l"(src));
        }
        asm volatile("cp.async.commit_group;");
    }

    const float4* xg = (const float4*)x;
    for (int i = tid; i < 64 * 32; i += 256) {
        int r = i >> 5, c4 = i & 31;
        int gr = rowBase + r;
        float4 v = (gr < N) ? __ldg(xg + (size_t)gr * 32 + c4) : make_float4(0.f, 0.f, 0.f, 0.f);
        ((float4*)Xs)[i] = v;
    }

    int tr = tid >> 5, tc = tid & 31;
    ull acc[8][3];
    #pragma unroll
    for (int i = 0; i < 8; i++)
        #pragma unroll
        for (int j = 0; j < 3; j++) acc[i][j] = 0ULL;

    for (int c = 0; c < NCH; c++) {
        int buf = c & 1;
        if (c + 1 < NCH) {
            int nb2 = buf ^ 1;
            for (int s = tid; s < KCH * 48; s += 256) {
                int mat = s / 512;
                int rem = s % 512;
                int k = rem >> 4;
                int f4 = rem & 15;
                const ull* src = (mat == 0 ? wsrc0 : mat == 1 ? wsrc1 : wsrc2)
                                 + (size_t)((c + 1) * KCH + k) * 32 + f4 * 2;
                unsigned int da = (unsigned int)__cvta_generic_to_shared(&Wsm[nb2][k][mat * 32 + f4 * 2]);
                asm volatile("cp.async.cg.shared.global [%0], [%1], 16;" :: "r"(da), "l"(src));
            }
            asm volatile("cp.async.commit_group;");
            asm volatile("cp.async.wait_group 1;");
        } else {
            asm volatile("cp.async.wait_group 0;");
        }
        __syncthreads();

        ull wA[12];
        #pragma unroll
        for (int kk = 0; kk < 4; kk++) {
            wA[kk]     = Wsm[buf][kk][tc];
            wA[4 + kk] = Wsm[buf][kk][32 + tc];
            wA[8 + kk] = Wsm[buf][kk][64 + tc];
        }
        #pragma unroll
        for (int k0 = 0; k0 < KCH; k0 += 4) {
            ull wB[12];
            if (k0 + 4 < KCH) {
                #pragma unroll
                for (int kk = 0; kk < 4; kk++) {
                    wB[kk]     = Wsm[buf][k0 + 4 + kk][tc];
                    wB[4 + kk] = Wsm[buf][k0 + 4 + kk][32 + tc];
                    wB[8 + kk] = Wsm[buf][k0 + 4 + kk][64 + tc];
                }
            }
            #pragma unroll
            for (int grp = 0; grp < 2; grp++) {
                float4 av[4];
                #pragma unroll
                for (int i = 0; i < 4; i++)
                    av[i] = *(const float4*)&Xs[(tr * 8 + grp * 4 + i) * 128 + c * KCH + k0];
                #pragma unroll
                for (int kk = 0; kk < 4; kk++) {
                    #pragma unroll
                    for (int i = 0; i < 4; i++) {
                        float a = (kk == 0) ? av[i].x : (kk == 1) ? av[i].y : (kk == 2) ? av[i].z : av[i].w;
                        ull ad = pack_dup(a);
                        int row = grp * 4 + i;
                        fma2(acc[row][0], ad, wA[kk]);
                        fma2(acc[row][1], ad, wA[4 + kk]);
                        fma2(acc[row][2], ad, wA[8 + kk]);
                    }
                }
            }
            if (k0 + 4 < KCH) {
                #pragma unroll
                for (int j = 0; j < 12; j++) wA[j] = wB[j];
            }
        }
        __syncthreads();
    }

    float sb0 = __ldg(skip_b + 2 * tc), sb1 = __ldg(skip_b + 2 * tc + 1);
    #pragma unroll
    for (int i = 0; i < 8; i++) {
        int gr = rowBase + tr * 8 + i;
        if (gr >= N) break;
        ((ull*)g_xl)[(size_t)gr * 32 + tc] = acc[i][0];
        ((ull*)g_xr)[(size_t)gr * 32 + tc] = acc[i][1];
        float lo, hi; unpack2(acc[i][2], lo, hi);
        float2 o; o.x = lo + sb0; o.y = hi + sb1;
        ((float2*)g_xs)[(size_t)gr * 32 + tc] = o;
    }
}

// ---------------- K2: per-dst softmax-aggregate, no-max, 2 edges/warp, float4 ----------------
__global__ __launch_bounds__(256) void k_edge(
    const float* __restrict__ att, const float* __restrict__ conv_bias, int N, int E)
{
    int gw = (blockIdx.x * blockDim.x + threadIdx.x) >> 5;
    if (gw >= N) return;
    int lane = threadIdx.x & 31;
    int half = lane >> 4;
    int l = lane & 15;
    int d = gw;
    unsigned hmask = half ? 0xFFFF0000u : 0x0000FFFFu;

    const float4* xl4 = (const float4*)g_xl;
    float4 xr = __ldg((const float4*)g_xr + (size_t)d * 16 + l);
    float4 at = __ldg((const float4*)att + l);

    float den = 0.f, s0 = 0.f, s1 = 0.f, s2 = 0.f, s3 = 0.f;

    int e0  = g_off[d];
    int end = (d + 1 < N) ? g_off[d + 1] : E;
    int nE  = end - e0;
    int cnt = (nE - half + 1) >> 1;
    if (cnt < 0) cnt = 0;
    int base = e0 + half;

    if (half == 1) {
        float4 v = __ldg(xl4 + (size_t)d * 16 + l);
        float t0 = v.x + xr.x, t1 = v.y + xr.y, t2 = v.z + xr.z, t3 = v.w + xr.w;
        t0 = t0 > 0.f ? t0 : 0.2f * t0;
        t1 = t1 > 0.f ? t1 : 0.2f * t1;
        t2 = t2 > 0.f ? t2 : 0.2f * t2;
        t3 = t3 > 0.f ? t3 : 0.2f * t3;
        float p = fmaf(t0, at.x, fmaf(t1, at.y, fmaf(t2, at.z, t3 * at.w)));
        p += __shfl_xor_sync(hmask, p, 1);
        p += __shfl_xor_sync(hmask, p, 2);
        float ex = __expf(p);
        den += ex;
        s0 = fmaf(v.x, ex, s0);
        s1 = fmaf(v.y, ex, s1);
        s2 = fmaf(v.z, ex, s2);
        s3 = fmaf(v.w, ex, s3);
    } else {
        float p = 0.f;
        p += __shfl_xor_sync(hmask, p, 1);
        p += __shfl_xor_sync(hmask, p, 2);
    }

    #pragma unroll 4
    for (int it = 0; it < cnt; it++) {
        int src = __ldg(&g_csr[base + 2 * it]);
        float4 v = __ldg(xl4 + (size_t)src * 16 + l);
        float t0 = v.x + xr.x, t1 = v.y + xr.y, t2 = v.z + xr.z, t3 = v.w + xr.w;
        t0 = t0 > 0.f ? t0 : 0.2f * t0;
        t1 = t1 > 0.f ? t1 : 0.2f * t1;
        t2 = t2 > 0.f ? t2 : 0.2f * t2;
        t3 = t3 > 0.f ? t3 : 0.2f * t3;
        float p = fmaf(t0, at.x, fmaf(t1, at.y, fmaf(t2, at.z, t3 * at.w)));
        p += __shfl_xor_sync(hmask, p, 1);
        p += __shfl_xor_sync(hmask, p, 2);
        float ex = __expf(p);
        den += ex;
        s0 = fmaf(v.x, ex, s0);
        s1 = fmaf(v.y, ex, s1);
        s2 = fmaf(v.z, ex, s2);
        s3 = fmaf(v.w, ex, s3);
    }

    __syncwarp();
    den += __shfl_xor_sync(0xffffffffu, den, 16);
    s0  += __shfl_xor_sync(0xffffffffu, s0, 16);
    s1  += __shfl_xor_sync(0xffffffffu, s1, 16);
    s2  += __shfl_xor_sync(0xffffffffu, s2, 16);
    s3  += __shfl_xor_sync(0xffffffffu, s3, 16);

    if (half == 0) {
        float inv = 1.f / den;
        float4 cb = __ldg((const float4*)conv_bias + l);
        float4 o;
        o.x = fmaf(s0, inv, cb.x);
        o.y = fmaf(s1, inv, cb.y);
        o.z = fmaf(s2, inv, cb.z);
        o.w = fmaf(s3, inv, cb.w);
        ((float4*)g_out)[(size_t)d * 16 + l] = o;
    }
}

// ---------------- K3a: skip-branch sums (only needs gemm) ----------------
__global__ __launch_bounds__(256) void k_statsS(const int* __restrict__ batch, int N)
{
    int gid = blockIdx.x * blockDim.x + threadIdx.x;
    int ch = gid & 63;
    int slot = gid >> 6;
    int n0 = slot * 32;
    if (n0 >= N) return;
    int n1 = min(n0 + 32, N);

    int gfirst = batch[n0], glast = batch[n1 - 1];
    if (gfirst == glast) {
        float aS = 0.f, qS = 0.f;
        #pragma unroll 4
        for (int n = n0; n < n1; n++) {
            float vs = g_xs[(size_t)n * 64 + ch];
            aS += vs; qS = fmaf(vs, vs, qS);
        }
        atomicAdd(&g_sumS[gfirst * 64 + ch], aS);
        atomicAdd(&g_sqS [gfirst * 64 + ch], qS);
        if (ch == 0) atomicAdd(&g_cnt[gfirst], (float)(n1 - n0));
        return;
    }

    float aS = 0.f, qS = 0.f, ac = 0.f;
    int curg = gfirst;
    for (int n = n0; n < n1; n++) {
        int g = batch[n];
        if (g != curg) {
            atomicAdd(&g_sumS[curg * 64 + ch], aS);
            atomicAdd(&g_sqS [curg * 64 + ch], qS);
            if (ch == 0) atomicAdd(&g_cnt[curg], ac);
            aS = qS = ac = 0.f; curg = g;
        }
        float vs = g_xs[(size_t)n * 64 + ch];
        aS += vs; qS = fmaf(vs, vs, qS);
        ac += 1.f;
    }
    atomicAdd(&g_sumS[curg * 64 + ch], aS);
    atomicAdd(&g_sqS [curg * 64 + ch], qS);
    if (ch == 0) atomicAdd(&g_cnt[curg], ac);
}

// ---------------- K3b: main-branch sums (needs edge output) ----------------
__global__ __launch_bounds__(256) void k_statsM(const int* __restrict__ batch, int N)
{
    int gid = blockIdx.x * blockDim.x + threadIdx.x;
    int ch = gid & 63;
    int slot = gid >> 6;
    int n0 = slot * 32;
    if (n0 >= N) return;
    int n1 = min(n0 + 32, N);

    int gfirst = batch[n0], glast = batch[n1 - 1];
    if (gfirst == glast) {
        float aM = 0.f, qM = 0.f;
        #pragma unroll 4
        for (int n = n0; n < n1; n++) {
            float vm = g_out[(size_t)n * 64 + ch];
            aM += vm; qM = fmaf(vm, vm, qM);
        }
        atomicAdd(&g_sumM[gfirst * 64 + ch], aM);
        atomicAdd(&g_sqM [gfirst * 64 + ch], qM);
        return;
    }

    float aM = 0.f, qM = 0.f;
    int curg = gfirst;
    for (int n = n0; n < n1; n++) {
        int g = batch[n];
        if (g != curg) {
            atomicAdd(&g_sumM[curg * 64 + ch], aM);
            atomicAdd(&g_sqM [curg * 64 + ch], qM);
            aM = qM = 0.f; curg = g;
        }
        float vm = g_out[(size_t)n * 64 + ch];
        aM += vm; qM = fmaf(vm, vm, qM);
    }
    atomicAdd(&g_sumM[curg * 64 + ch], aM);
    atomicAdd(&g_sqM [curg * 64 + ch], qM);
}

// ---------------- K3c: precompute per-(graph,channel) affine coeffs ----------------
__global__ void k_prec(
    const float* __restrict__ bn_w, const float* __restrict__ bn_b, const float* __restrict__ bn_ms,
    const float* __restrict__ sn_w, const float* __restrict__ sn_b, const float* __restrict__ sn_ms)
{
    int i = blockIdx.x * blockDim.x + threadIdx.x;
    if (i >= G_NUM * 64) return;
    int g = i >> 6, ch = i & 63;
    float cntv = fmaxf(g_cnt[g], 1.f);
    float rinv = 1.f / cntv;
    float msM = bn_ms[ch], msS = sn_ms[ch];

    float meanM = g_sumM[i] * rinv;
    float eqM   = g_sqM [i] * rinv;
    float varM  = fmaxf(eqM - meanM * meanM * msM * (2.f - msM), 0.f);
    float meanS = g_sumS[i] * rinv;
    float eqS   = g_sqS [i] * rinv;
    float varS  = fmaxf(eqS - meanS * meanS * msS * (2.f - msS), 0.f);

    float cM = bn_w[ch] * rsqrtf(varM + 1e-5f);
    float cS = sn_w[ch] * rsqrtf(varS + 1e-5f);
    float C  = bn_b[ch] + sn_b[ch] - cM * meanM * msM - cS * meanS * msS;
    g_sumM[i] = cM;
    g_sumS[i] = cS;
    g_sqM [i] = C;
}

// ---------------- K4: y = cM*vm + cS*vs + C, then ELU (float4) ----------------
__global__ __launch_bounds__(256) void k_final(
    const int* __restrict__ batch, float* __restrict__ out, int N)
{
    int i = blockIdx.x * blockDim.x + threadIdx.x;
    if (i >= N * 16) return;
    int n = i >> 4, q = i & 15;
    int g = batch[n];

    float4 cM = ((const float4*)g_sumM)[g * 16 + q];
    float4 cS = ((const float4*)g_sumS)[g * 16 + q];
    float4 C  = ((const float4*)g_sqM )[g * 16 + q];
    float4 vm = ((const float4*)g_out)[i];
    float4 vs = ((const float4*)g_xs)[i];

    float4 res;
    float y;
    y = fmaf(cM.x, vm.x, fmaf(cS.x, vs.x, C.x)); res.x = (y > 0.f) ? y : (__expf(y) - 1.f);
    y = fmaf(cM.y, vm.y, fmaf(cS.y, vs.y, C.y)); res.y = (y > 0.f) ? y : (__expf(y) - 1.f);
    y = fmaf(cM.z, vm.z, fmaf(cS.z, vs.z, C.z)); res.z = (y > 0.f) ? y : (__expf(y) - 1.f);
    y = fmaf(cM.w, vm.w, fmaf(cS.w, vs.w, C.w)); res.w = (y > 0.f) ? y : (__expf(y) - 1.f);
    ((float4*)out)[i] = res;
}

// ---------------- launch (fork-join: CSR+statsS overlap GEMM+edge) ----------------
extern "C" void kernel_launch(void* const* d_in, const int* in_sizes, int n_in,
                              void* d_out, int out_size)
{
    const float* x         = (const float*)d_in[0];
    const int*   ei        = (const int*)d_in[1];
    const int*   batch     = (const int*)d_in[2];
    const float* Wl        = (const float*)d_in[3];
    const float* Wr        = (const float*)d_in[4];
    const float* att       = (const float*)d_in[5];
    const float* conv_bias = (const float*)d_in[6];
    const float* skip_W    = (const float*)d_in[7];
    const float* skip_b    = (const float*)d_in[8];
    const float* bn_w      = (const float*)d_in[9];
    const float* bn_b      = (const float*)d_in[10];
    const float* bn_ms     = (const float*)d_in[11];
    const float* sn_w      = (const float*)d_in[12];
    const float* sn_b      = (const float*)d_in[13];
    const float* sn_ms     = (const float*)d_in[14];
    float*       out       = (float*)d_out;

    int N  = in_sizes[0] / 128;
    int E  = in_sizes[1] / 2;
    int nb = (N + 1023) / 1024;

    static cudaStream_t s1 = nullptr;
    static cudaEvent_t evFork = nullptr, evJoin = nullptr, evGemm = nullptr, evS = nullptr;
    if (s1 == nullptr) {
        cudaStreamCreateWithFlags(&s1, cudaStreamNonBlocking);
        cudaEventCreateWithFlags(&evFork, cudaEventDisableTiming);
        cudaEventCreateWithFlags(&evJoin, cudaEventDisableTiming);
        cudaEventCreateWithFlags(&evGemm, cudaEventDisableTiming);
        cudaEventCreateWithFlags(&evS, cudaEventDisableTiming);
    }

    // fork: CSR build chain on s1, GEMM on the main (capture) stream
    cudaEventRecord(evFork, 0);
    cudaStreamWaitEvent(s1, evFork, 0);

    k_init <<<(N + 255) / 256, 256, 0, s1>>>(N);
    k_hist <<<(E + 255) / 256, 256, 0, s1>>>(ei, E);
    k_scan1<<<nb, 1024, 0, s1>>>(N);
    k_scan2<<<1, 1024, 0, s1>>>(nb);
    k_scan3<<<(N + 255) / 256, 256, 0, s1>>>(N);
    k_fill <<<(E + 255) / 256, 256, 0, s1>>>(ei, E);
    cudaEventRecord(evJoin, s1);

    k_gemm <<<(N + 63) / 64, 256>>>(x, Wl, Wr, skip_W, skip_b, N);
    cudaEventRecord(evGemm, 0);

    // statsS overlaps edge on side stream (needs gemm output + init)
    cudaStreamWaitEvent(s1, evGemm, 0);
    {
        int slots = (N + 31) / 32;
        long long threads = (long long)slots * 64;
        k_statsS<<<(unsigned)((threads + 255) / 256), 256, 0, s1>>>(batch, N);
    }
    cudaEventRecord(evS, s1);

    // join: edge needs both GEMM output and CSR
    cudaStreamWaitEvent(0, evJoin, 0);

    {   // edge: 1 warp per node
        long long threads = (long long)N * 32;
        k_edge<<<(unsigned)((threads + 255) / 256), 256>>>(att, conv_bias, N, E);
    }
    {   // statsM (main branch)
        int slots = (N + 31) / 32;
        long long threads = (long long)slots * 64;
        k_statsM<<<(unsigned)((threads + 255) / 256), 256>>>(batch, N);
    }
    cudaStreamWaitEvent(0, evS, 0);
    k_prec<<<(G_NUM * 64 + 255) / 256, 256>>>(bn_w, bn_b, bn_ms, sn_w, sn_b, sn_ms);
    {   // final
        long long total = (long long)N * 16;
        k_final<<<(unsigned)((total + 255) / 256), 256>>>(batch, out, N);
    }
}

// round 13
// speedup vs baseline: 1.5921x; 1.2810x over previous
#include <cuda_runtime.h>
#include <cuda_bf16.h>
#include <cstdint>
#include <math.h>

#define N_MAX   100000
#define E_MAX   1600000
#define G_NUM   64

typedef unsigned long long ull;

// ---------------- scratch (device globals; no allocation) ----------------
__device__ __align__(16) float g_xl[N_MAX * 64];
__device__ __align__(16) float g_xr[N_MAX * 64];
__device__ __align__(16) float g_xs[N_MAX * 64];
__device__ __align__(16) float g_out[N_MAX * 64];
__device__ int   g_deg[N_MAX];
__device__ int   g_off[N_MAX];
__device__ int   g_cur[N_MAX];
__device__ int   g_csr[E_MAX];
__device__ int   g_bsum[1024];
__device__ float g_sumM[G_NUM * 64];
__device__ float g_sqM [G_NUM * 64];
__device__ float g_sumS[G_NUM * 64];
__device__ float g_sqS [G_NUM * 64];
__device__ float g_cnt [G_NUM];
// bf16 hi/lo weight fragments in m16n8k16 B-layout: [ks(8)][nt(24)][lane(32)]{b0h,b1h,b0l,b1l}
__device__ __align__(16) uint4 g_wfrag[8 * 24 * 32];

// ---------------- helpers ----------------
__device__ __forceinline__ uint32_t f2bf2(float a, float b) {
    __nv_bfloat162 t = __floats2bfloat162_rn(a, b);   // .x = a = low half
    uint32_t r; memcpy(&r, &t, 4); return r;
}
__device__ __forceinline__ void bf2_split(float x0, float x1, uint32_t& hi, uint32_t& lo) {
    hi = f2bf2(x0, x1);
    float h0 = __uint_as_float(hi << 16);
    float h1 = __uint_as_float(hi & 0xFFFF0000u);
    lo = f2bf2(x0 - h0, x1 - h1);
}
__device__ __forceinline__ void mma16816(float* d, const uint32_t* a, uint32_t b0, uint32_t b1) {
    asm volatile(
        "mma.sync.aligned.m16n8k16.row.col.f32.bf16.bf16.f32 "
        "{%0,%1,%2,%3}, {%4,%5,%6,%7}, {%8,%9}, {%0,%1,%2,%3};"
        : "+f"(d[0]), "+f"(d[1]), "+f"(d[2]), "+f"(d[3])
        : "r"(a[0]), "r"(a[1]), "r"(a[2]), "r"(a[3]), "r"(b0), "r"(b1));
}

// ---------------- K0: init ----------------
__global__ void k_init(int N) {
    int i = blockIdx.x * blockDim.x + threadIdx.x;
    if (i < N) g_deg[i] = 0;
    if (i < G_NUM * 64) { g_sumM[i] = 0.f; g_sqM[i] = 0.f; g_sumS[i] = 0.f; g_sqS[i] = 0.f; }
    if (i < G_NUM) g_cnt[i] = 0.f;
}
__global__ void k_hist(const int* __restrict__ ei, int E) {
    int i = blockIdx.x * blockDim.x + threadIdx.x;
    if (i < E) atomicAdd(&g_deg[ei[E + i]], 1);
}

__global__ __launch_bounds__(1024) void k_scan1(int N) {
    __shared__ int s[1024];
    int tid = threadIdx.x;
    int i = blockIdx.x * 1024 + tid;
    int v = (i < N) ? g_deg[i] : 0;
    s[tid] = v;
    #pragma unroll
    for (int d = 1; d < 1024; d <<= 1) {
        __syncthreads();
        int t = (tid >= d) ? s[tid - d] : 0;
        __syncthreads();
        s[tid] += t;
    }
    __syncthreads();
    if (i < N) g_off[i] = s[tid] - v;
    if (tid == 1023) g_bsum[blockIdx.x] = s[1023];
}

__global__ __launch_bounds__(1024) void k_scan2(int nb) {
    __shared__ int s[1024];
    int tid = threadIdx.x;
    int v = (tid < nb) ? g_bsum[tid] : 0;
    s[tid] = v;
    #pragma unroll
    for (int d = 1; d < 1024; d <<= 1) {
        __syncthreads();
        int t = (tid >= d) ? s[tid - d] : 0;
        __syncthreads();
        s[tid] += t;
    }
    __syncthreads();
    if (tid < nb) g_bsum[tid] = s[tid] - v;
}

__global__ void k_scan3(int N) {
    int i = blockIdx.x * blockDim.x + threadIdx.x;
    if (i >= N) return;
    int o = g_off[i] + g_bsum[i >> 10];
    g_off[i] = o;
    g_cur[i] = o;
}

__global__ void k_fill(const int* __restrict__ ei, int E) {
    int i = blockIdx.x * blockDim.x + threadIdx.x;
    if (i >= E) return;
    int dst = ei[E + i];
    int pos = atomicAdd(&g_cur[dst], 1);
    g_csr[pos] = ei[i];
}

// ---------------- K_wprep: W -> bf16 hi/lo mma B-fragments ----------------
// B(k,n) = W[k][n], n in [0,192): 0-63 Wl, 64-127 Wr, 128-191 Ws.
// fragment (ks, nt, lane): g=lane>>2, t=lane&3; n = nt*8+g; k0 = ks*16+2t;
// b0 = {B(k0,n),B(k0+1,n)}, b1 = {B(k0+8,n),B(k0+9,n)}.
__global__ void k_wprep(const float* __restrict__ Wl, const float* __restrict__ Wr,
                        const float* __restrict__ Ws) {
    int idx = blockIdx.x * blockDim.x + threadIdx.x;
    if (idx >= 8 * 24 * 32) return;
    int lane = idx & 31;
    int nt = (idx >> 5) % 24;
    int ks = idx / (24 * 32);
    int g = lane >> 2, t = lane & 3;
    int n = nt * 8 + g;
    int k0 = ks * 16 + 2 * t;
    const float* W = (n < 64) ? Wl : ((n < 128) ? Wr : Ws);
    int wn = n & 63;
    float x0 = __ldg(W + (k0)     * 64 + wn);
    float x1 = __ldg(W + (k0 + 1) * 64 + wn);
    float x2 = __ldg(W + (k0 + 8) * 64 + wn);
    float x3 = __ldg(W + (k0 + 9) * 64 + wn);
    uint4 o;
    uint32_t h, l;
    bf2_split(x0, x1, h, l); o.x = h; o.z = l;
    bf2_split(x2, x3, h, l); o.y = h; o.w = l;
    g_wfrag[idx] = o;
}

// ---------------- K1: mma.sync bf16x3 GEMM  [xl|xr|xs] = X @ [Wl|Wr|Ws] ----------------
// block: 256 thr = 8 warps = 4 row-strips x 2 col-halves; 64 rows x 192 cols per block.
#define WSMEM (8 * 24 * 32 * 16)   // 98304
__global__ __launch_bounds__(256) void k_gemmT(
    const float* __restrict__ x, const float* __restrict__ skip_b, int N)
{
    extern __shared__ uint4 sB[];   // [ks][nt][lane] 16B each
    int tid = threadIdx.x;
    int warp = tid >> 5, lane = tid & 31;
    int strip = warp & 3, colhalf = warp >> 2;
    int g = lane >> 2, t = lane & 3;

    // stage B fragments
    for (int i = tid; i < 8 * 24 * 32; i += 256) {
        unsigned int da;
        asm("{ .reg .u64 u; cvta.to.shared.u64 u, %1; cvt.u32.u64 %0, u; }"
            : "=r"(da) : "l"(sB + i));
        const uint4* src = g_wfrag + i;
        asm volatile("cp.async.cg.shared.global [%0], [%1], 16;" :: "r"(da), "l"(src));
    }
    asm volatile("cp.async.commit_group;");

    int R = blockIdx.x * 64 + strip * 16;
    int rA = R + g, rB = R + 8 + g;
    bool vA = rA < N, vB = rB < N;
    const float* xA = x + (size_t)rA * 128;
    const float* xB = x + (size_t)rB * 128;

    float D[12][4];
    #pragma unroll
    for (int i = 0; i < 12; i++)
        #pragma unroll
        for (int j = 0; j < 4; j++) D[i][j] = 0.f;

    asm volatile("cp.async.wait_group 0;");
    __syncthreads();

    #pragma unroll 1
    for (int ks = 0; ks < 8; ks++) {
        int kb = ks * 16 + 2 * t;
        float2 z = make_float2(0.f, 0.f);
        float2 p0 = vA ? *(const float2*)(xA + kb)     : z;
        float2 p2 = vA ? *(const float2*)(xA + kb + 8) : z;
        float2 p1 = vB ? *(const float2*)(xB + kb)     : z;
        float2 p3 = vB ? *(const float2*)(xB + kb + 8) : z;

        uint32_t ah[4], al[4];
        bf2_split(p0.x, p0.y, ah[0], al[0]);
        bf2_split(p1.x, p1.y, ah[1], al[1]);
        bf2_split(p2.x, p2.y, ah[2], al[2]);
        bf2_split(p3.x, p3.y, ah[3], al[3]);

        const uint4* bp = sB + (ks * 24 + colhalf * 12) * 32 + lane;
        #pragma unroll
        for (int nt = 0; nt < 12; nt++) {
            uint4 B4 = bp[nt * 32];
            mma16816(D[nt], ah, B4.x, B4.y);   // Ah * Bh
            mma16816(D[nt], ah, B4.z, B4.w);   // Ah * Bl
            mma16816(D[nt], al, B4.x, B4.y);   // Al * Bh
        }
    }

    // epilogue
    #pragma unroll
    for (int nt = 0; nt < 12; nt++) {
        int cbase = (colhalf * 12 + nt) * 8;
        float* dst = (cbase < 64) ? g_xl : ((cbase < 128) ? g_xr : g_xs);
        int c = (cbase & 63) + 2 * t;
        float add0 = 0.f, add1 = 0.f;
        if (cbase >= 128) { add0 = __ldg(skip_b + c); add1 = __ldg(skip_b + c + 1); }
        if (vA) {
            float2 v; v.x = D[nt][0] + add0; v.y = D[nt][1] + add1;
            *(float2*)(dst + (size_t)rA * 64 + c) = v;
        }
        if (vB) {
            float2 v; v.x = D[nt][2] + add0; v.y = D[nt][3] + add1;
            *(float2*)(dst + (size_t)rB * 64 + c) = v;
        }
    }
}

// ---------------- K2: per-dst softmax-aggregate, no-max, 2 edges/warp, float4 ----------------
__global__ __launch_bounds__(256) void k_edge(
    const float* __restrict__ att, const float* __restrict__ conv_bias, int N, int E)
{
    int gw = (blockIdx.x * blockDim.x + threadIdx.x) >> 5;
    if (gw >= N) return;
    int lane = threadIdx.x & 31;
    int half = lane >> 4;
    int l = lane & 15;
    int d = gw;
    unsigned hmask = half ? 0xFFFF0000u : 0x0000FFFFu;

    const float4* xl4 = (const float4*)g_xl;
    float4 xr = __ldg((const float4*)g_xr + (size_t)d * 16 + l);
    float4 at = __ldg((const float4*)att + l);

    float den = 0.f, s0 = 0.f, s1 = 0.f, s2 = 0.f, s3 = 0.f;

    int e0  = g_off[d];
    int end = (d + 1 < N) ? g_off[d + 1] : E;
    int nE  = end - e0;
    int cnt = (nE - half + 1) >> 1;
    if (cnt < 0) cnt = 0;
    int base = e0 + half;

    if (half == 1) {
        float4 v = __ldg(xl4 + (size_t)d * 16 + l);
        float t0 = v.x + xr.x, t1 = v.y + xr.y, t2 = v.z + xr.z, t3 = v.w + xr.w;
        t0 = t0 > 0.f ? t0 : 0.2f * t0;
        t1 = t1 > 0.f ? t1 : 0.2f * t1;
        t2 = t2 > 0.f ? t2 : 0.2f * t2;
        t3 = t3 > 0.f ? t3 : 0.2f * t3;
        float p = fmaf(t0, at.x, fmaf(t1, at.y, fmaf(t2, at.z, t3 * at.w)));
        p += __shfl_xor_sync(hmask, p, 1);
        p += __shfl_xor_sync(hmask, p, 2);
        float ex = __expf(p);
        den += ex;
        s0 = fmaf(v.x, ex, s0);
        s1 = fmaf(v.y, ex, s1);
        s2 = fmaf(v.z, ex, s2);
        s3 = fmaf(v.w, ex, s3);
    } else {
        float p = 0.f;
        p += __shfl_xor_sync(hmask, p, 1);
        p += __shfl_xor_sync(hmask, p, 2);
    }

    #pragma unroll 4
    for (int it = 0; it < cnt; it++) {
        int src = __ldg(&g_csr[base + 2 * it]);
        float4 v = __ldg(xl4 + (size_t)src * 16 + l);
        float t0 = v.x + xr.x, t1 = v.y + xr.y, t2 = v.z + xr.z, t3 = v.w + xr.w;
        t0 = t0 > 0.f ? t0 : 0.2f * t0;
        t1 = t1 > 0.f ? t1 : 0.2f * t1;
        t2 = t2 > 0.f ? t2 : 0.2f * t2;
        t3 = t3 > 0.f ? t3 : 0.2f * t3;
        float p = fmaf(t0, at.x, fmaf(t1, at.y, fmaf(t2, at.z, t3 * at.w)));
        p += __shfl_xor_sync(hmask, p, 1);
        p += __shfl_xor_sync(hmask, p, 2);
        float ex = __expf(p);
        den += ex;
        s0 = fmaf(v.x, ex, s0);
        s1 = fmaf(v.y, ex, s1);
        s2 = fmaf(v.z, ex, s2);
        s3 = fmaf(v.w, ex, s3);
    }

    __syncwarp();
    den += __shfl_xor_sync(0xffffffffu, den, 16);
    s0  += __shfl_xor_sync(0xffffffffu, s0, 16);
    s1  += __shfl_xor_sync(0xffffffffu, s1, 16);
    s2  += __shfl_xor_sync(0xffffffffu, s2, 16);
    s3  += __shfl_xor_sync(0xffffffffu, s3, 16);

    if (half == 0) {
        float inv = 1.f / den;
        float4 cb = __ldg((const float4*)conv_bias + l);
        float4 o;
        o.x = fmaf(s0, inv, cb.x);
        o.y = fmaf(s1, inv, cb.y);
        o.z = fmaf(s2, inv, cb.z);
        o.w = fmaf(s3, inv, cb.w);
        ((float4*)g_out)[(size_t)d * 16 + l] = o;
    }
}

// ---------------- K3a: skip-branch sums (only needs gemm) ----------------
__global__ __launch_bounds__(256) void k_statsS(const int* __restrict__ batch, int N)
{
    int gid = blockIdx.x * blockDim.x + threadIdx.x;
    int ch = gid & 63;
    int slot = gid >> 6;
    int n0 = slot * 32;
    if (n0 >= N) return;
    int n1 = min(n0 + 32, N);

    int gfirst = batch[n0], glast = batch[n1 - 1];
    if (gfirst == glast) {
        float aS = 0.f, qS = 0.f;
        #pragma unroll 4
        for (int n = n0; n < n1; n++) {
            float vs = g_xs[(size_t)n * 64 + ch];
            aS += vs; qS = fmaf(vs, vs, qS);
        }
        atomicAdd(&g_sumS[gfirst * 64 + ch], aS);
        atomicAdd(&g_sqS [gfirst * 64 + ch], qS);
        if (ch == 0) atomicAdd(&g_cnt[gfirst], (float)(n1 - n0));
        return;
    }

    float aS = 0.f, qS = 0.f, ac = 0.f;
    int curg = gfirst;
    for (int n = n0; n < n1; n++) {
        int g = batch[n];
        if (g != curg) {
            atomicAdd(&g_sumS[curg * 64 + ch], aS);
            atomicAdd(&g_sqS [curg * 64 + ch], qS);
            if (ch == 0) atomicAdd(&g_cnt[curg], ac);
            aS = qS = ac = 0.f; curg = g;
        }
        float vs = g_xs[(size_t)n * 64 + ch];
        aS += vs; qS = fmaf(vs, vs, qS);
        ac += 1.f;
    }
    atomicAdd(&g_sumS[curg * 64 + ch], aS);
    atomicAdd(&g_sqS [curg * 64 + ch], qS);
    if (ch == 0) atomicAdd(&g_cnt[curg], ac);
}

// ---------------- K3b: main-branch sums (needs edge output) ----------------
__global__ __launch_bounds__(256) void k_statsM(const int* __restrict__ batch, int N)
{
    int gid = blockIdx.x * blockDim.x + threadIdx.x;
    int ch = gid & 63;
    int slot = gid >> 6;
    int n0 = slot * 32;
    if (n0 >= N) return;
    int n1 = min(n0 + 32, N);

    int gfirst = batch[n0], glast = batch[n1 - 1];
    if (gfirst == glast) {
        float aM = 0.f, qM = 0.f;
        #pragma unroll 4
        for (int n = n0; n < n1; n++) {
            float vm = g_out[(size_t)n * 64 + ch];
            aM += vm; qM = fmaf(vm, vm, qM);
        }
        atomicAdd(&g_sumM[gfirst * 64 + ch], aM);
        atomicAdd(&g_sqM [gfirst * 64 + ch], qM);
        return;
    }

    float aM = 0.f, qM = 0.f;
    int curg = gfirst;
    for (int n = n0; n < n1; n++) {
        int g = batch[n];
        if (g != curg) {
            atomicAdd(&g_sumM[curg * 64 + ch], aM);
            atomicAdd(&g_sqM [curg * 64 + ch], qM);
            aM = qM = 0.f; curg = g;
        }
        float vm = g_out[(size_t)n * 64 + ch];
        aM += vm; qM = fmaf(vm, vm, qM);
    }
    atomicAdd(&g_sumM[curg * 64 + ch], aM);
    atomicAdd(&g_sqM [curg * 64 + ch], qM);
}

// ---------------- K3c: precompute per-(graph,channel) affine coeffs ----------------
__global__ void k_prec(
    const float* __restrict__ bn_w, const float* __restrict__ bn_b, const float* __restrict__ bn_ms,
    const float* __restrict__ sn_w, const float* __restrict__ sn_b, const float* __restrict__ sn_ms)
{
    int i = blockIdx.x * blockDim.x + threadIdx.x;
    if (i >= G_NUM * 64) return;
    int g = i >> 6, ch = i & 63;
    float cntv = fmaxf(g_cnt[g], 1.f);
    float rinv = 1.f / cntv;
    float msM = bn_ms[ch], msS = sn_ms[ch];

    float meanM = g_sumM[i] * rinv;
    float eqM   = g_sqM [i] * rinv;
    float varM  = fmaxf(eqM - meanM * meanM * msM * (2.f - msM), 0.f);
    float meanS = g_sumS[i] * rinv;
    float eqS   = g_sqS [i] * rinv;
    float varS  = fmaxf(eqS - meanS * meanS * msS * (2.f - msS), 0.f);

    float cM = bn_w[ch] * rsqrtf(varM + 1e-5f);
    float cS = sn_w[ch] * rsqrtf(varS + 1e-5f);
    float C  = bn_b[ch] + sn_b[ch] - cM * meanM * msM - cS * meanS * msS;
    g_sumM[i] = cM;
    g_sumS[i] = cS;
    g_sqM [i] = C;
}

// ---------------- K4: y = cM*vm + cS*vs + C, then ELU (float4) ----------------
__global__ __launch_bounds__(256) void k_final(
    const int* __restrict__ batch, float* __restrict__ out, int N)
{
    int i = blockIdx.x * blockDim.x + threadIdx.x;
    if (i >= N * 16) return;
    int n = i >> 4, q = i & 15;
    int g = batch[n];

    float4 cM = ((const float4*)g_sumM)[g * 16 + q];
    float4 cS = ((const float4*)g_sumS)[g * 16 + q];
    float4 C  = ((const float4*)g_sqM )[g * 16 + q];
    float4 vm = ((const float4*)g_out)[i];
    float4 vs = ((const float4*)g_xs)[i];

    float4 res;
    float y;
    y = fmaf(cM.x, vm.x, fmaf(cS.x, vs.x, C.x)); res.x = (y > 0.f) ? y : (__expf(y) - 1.f);
    y = fmaf(cM.y, vm.y, fmaf(cS.y, vs.y, C.y)); res.y = (y > 0.f) ? y : (__expf(y) - 1.f);
    y = fmaf(cM.z, vm.z, fmaf(cS.z, vs.z, C.z)); res.z = (y > 0.f) ? y : (__expf(y) - 1.f);
    y = fmaf(cM.w, vm.w, fmaf(cS.w, vs.w, C.w)); res.w = (y > 0.f) ? y : (__expf(y) - 1.f);
    ((float4*)out)[i] = res;
}

// ---------------- launch (fork-join: CSR+statsS overlap GEMM+edge) ----------------
extern "C" void kernel_launch(void* const* d_in, const int* in_sizes, int n_in,
                              void* d_out, int out_size)
{
    const float* x         = (const float*)d_in[0];
    const int*   ei        = (const int*)d_in[1];
    const int*   batch     = (const int*)d_in[2];
    const float* Wl        = (const float*)d_in[3];
    const float* Wr        = (const float*)d_in[4];
    const float* att       = (const float*)d_in[5];
    const float* conv_bias = (const float*)d_in[6];
    const float* skip_W    = (const float*)d_in[7];
    const float* skip_b    = (const float*)d_in[8];
    const float* bn_w      = (const float*)d_in[9];
    const float* bn_b      = (const float*)d_in[10];
    const float* bn_ms     = (const float*)d_in[11];
    const float* sn_w      = (const float*)d_in[12];
    const float* sn_b      = (const float*)d_in[13];
    const float* sn_ms     = (const float*)d_in[14];
    float*       out       = (float*)d_out;

    int N  = in_sizes[0] / 128;
    int E  = in_sizes[1] / 2;
    int nb = (N + 1023) / 1024;

    static cudaStream_t s1 = nullptr;
    static cudaEvent_t evFork = nullptr, evJoin = nullptr, evGemm = nullptr, evS = nullptr;
    if (s1 == nullptr) {
        cudaStreamCreateWithFlags(&s1, cudaStreamNonBlocking);
        cudaEventCreateWithFlags(&evFork, cudaEventDisableTiming);
        cudaEventCreateWithFlags(&evJoin, cudaEventDisableTiming);
        cudaEventCreateWithFlags(&evGemm, cudaEventDisableTiming);
        cudaEventCreateWithFlags(&evS, cudaEventDisableTiming);
        cudaFuncSetAttribute(k_gemmT, cudaFuncAttributeMaxDynamicSharedMemorySize, WSMEM);
    }

    // fork: CSR build chain on s1
    cudaEventRecord(evFork, 0);
    cudaStreamWaitEvent(s1, evFork, 0);

    k_init <<<(N + 255) / 256, 256, 0, s1>>>(N);
    k_hist <<<(E + 255) / 256, 256, 0, s1>>>(ei, E);
    k_scan1<<<nb, 1024, 0, s1>>>(N);
    k_scan2<<<1, 1024, 0, s1>>>(nb);
    k_scan3<<<(N + 255) / 256, 256, 0, s1>>>(N);
    k_fill <<<(E + 255) / 256, 256, 0, s1>>>(ei, E);
    cudaEventRecord(evJoin, s1);

    // main: weight fragment prep + tensor-core GEMM
    k_wprep<<<(8 * 24 * 32 + 255) / 256, 256>>>(Wl, Wr, skip_W);
    k_gemmT<<<(N + 63) / 64, 256, WSMEM>>>(x, skip_b, N);
    cudaEventRecord(evGemm, 0);

    // statsS overlaps edge on side stream
    cudaStreamWaitEvent(s1, evGemm, 0);
    {
        int slots = (N + 31) / 32;
        long long threads = (long long)slots * 64;
        k_statsS<<<(unsigned)((threads + 255) / 256), 256, 0, s1>>>(batch, N);
    }
    cudaEventRecord(evS, s1);

    // join: edge needs both GEMM output and CSR
    cudaStreamWaitEvent(0, evJoin, 0);

    {   // edge: 1 warp per node
        long long threads = (long long)N * 32;
        k_edge<<<(unsigned)((threads + 255) / 256), 256>>>(att, conv_bias, N, E);
    }
    {   // statsM
        int slots = (N + 31) / 32;
        long long threads = (long long)slots * 64;
        k_statsM<<<(unsigned)((threads + 255) / 256), 256>>>(batch, N);
    }
    cudaStreamWaitEvent(0, evS, 0);
    k_prec<<<(G_NUM * 64 + 255) / 256, 256>>>(bn_w, bn_b, bn_ms, sn_w, sn_b, sn_ms);
    {   // final
        long long total = (long long)N * 16;
        k_final<<<(unsigned)((total + 255) / 256), 256>>>(batch, out, N);
    }
}

// round 14
// speedup vs baseline: 1.6014x; 1.0058x over previous
#include <cuda_runtime.h>
#include <cuda_bf16.h>
#include <cstdint>
#include <math.h>

#define N_MAX   100000
#define E_MAX   1600000
#define G_NUM   64

typedef unsigned long long ull;

// ---------------- scratch (device globals; no allocation) ----------------
__device__ __align__(16) float g_xl[N_MAX * 64];
__device__ __align__(16) float g_xr[N_MAX * 64];
__device__ __align__(16) float g_xs[N_MAX * 64];
__device__ __align__(16) float g_out[N_MAX * 64];
__device__ int   g_deg[N_MAX];
__device__ int   g_off[N_MAX];
__device__ int   g_cur[N_MAX];
__device__ int   g_csr[E_MAX];
__device__ int   g_bsum[1024];
__device__ float g_sumM[G_NUM * 64];
__device__ float g_sqM [G_NUM * 64];
__device__ float g_sumS[G_NUM * 64];
__device__ float g_sqS [G_NUM * 64];
__device__ float g_cnt [G_NUM];
// bf16 hi/lo weight fragments in m16n8k16 B-layout: [ks(8)][nt(24)][lane(32)]{b0h,b1h,b0l,b1l}
__device__ __align__(16) uint4 g_wfrag[8 * 24 * 32];

// ---------------- helpers ----------------
__device__ __forceinline__ uint32_t f2bf2(float a, float b) {
    __nv_bfloat162 t = __floats2bfloat162_rn(a, b);   // .x = a = low half
    uint32_t r; memcpy(&r, &t, 4); return r;
}
__device__ __forceinline__ void bf2_split(float x0, float x1, uint32_t& hi, uint32_t& lo) {
    hi = f2bf2(x0, x1);
    float h0 = __uint_as_float(hi << 16);
    float h1 = __uint_as_float(hi & 0xFFFF0000u);
    lo = f2bf2(x0 - h0, x1 - h1);
}
__device__ __forceinline__ void mma16816(float* d, const uint32_t* a, uint32_t b0, uint32_t b1) {
    asm volatile(
        "mma.sync.aligned.m16n8k16.row.col.f32.bf16.bf16.f32 "
        "{%0,%1,%2,%3}, {%4,%5,%6,%7}, {%8,%9}, {%0,%1,%2,%3};"
        : "+f"(d[0]), "+f"(d[1]), "+f"(d[2]), "+f"(d[3])
        : "r"(a[0]), "r"(a[1]), "r"(a[2]), "r"(a[3]), "r"(b0), "r"(b1));
}

// ---------------- K0: init ----------------
__global__ void k_init(int N) {
    int i = blockIdx.x * blockDim.x + threadIdx.x;
    if (i < N) g_deg[i] = 0;
    if (i < G_NUM * 64) { g_sumM[i] = 0.f; g_sqM[i] = 0.f; g_sumS[i] = 0.f; g_sqS[i] = 0.f; }
    if (i < G_NUM) g_cnt[i] = 0.f;
}
__global__ void k_hist(const int* __restrict__ ei, int E) {
    int i = blockIdx.x * blockDim.x + threadIdx.x;
    if (i < E) atomicAdd(&g_deg[ei[E + i]], 1);
}

__global__ __launch_bounds__(1024) void k_scan1(int N) {
    __shared__ int s[1024];
    int tid = threadIdx.x;
    int i = blockIdx.x * 1024 + tid;
    int v = (i < N) ? g_deg[i] : 0;
    s[tid] = v;
    #pragma unroll
    for (int d = 1; d < 1024; d <<= 1) {
        __syncthreads();
        int t = (tid >= d) ? s[tid - d] : 0;
        __syncthreads();
        s[tid] += t;
    }
    __syncthreads();
    if (i < N) g_off[i] = s[tid] - v;
    if (tid == 1023) g_bsum[blockIdx.x] = s[1023];
}

__global__ __launch_bounds__(1024) void k_scan2(int nb) {
    __shared__ int s[1024];
    int tid = threadIdx.x;
    int v = (tid < nb) ? g_bsum[tid] : 0;
    s[tid] = v;
    #pragma unroll
    for (int d = 1; d < 1024; d <<= 1) {
        __syncthreads();
        int t = (tid >= d) ? s[tid - d] : 0;
        __syncthreads();
        s[tid] += t;
    }
    __syncthreads();
    if (tid < nb) g_bsum[tid] = s[tid] - v;
}

__global__ void k_scan3(int N) {
    int i = blockIdx.x * blockDim.x + threadIdx.x;
    if (i >= N) return;
    int o = g_off[i] + g_bsum[i >> 10];
    g_off[i] = o;
    g_cur[i] = o;
}

__global__ void k_fill(const int* __restrict__ ei, int E) {
    int i = blockIdx.x * blockDim.x + threadIdx.x;
    if (i >= E) return;
    int dst = ei[E + i];
    int pos = atomicAdd(&g_cur[dst], 1);
    g_csr[pos] = ei[i];
}

// ---------------- K_wprep: W -> bf16 hi/lo mma B-fragments ----------------
__global__ void k_wprep(const float* __restrict__ Wl, const float* __restrict__ Wr,
                        const float* __restrict__ Ws) {
    int idx = blockIdx.x * blockDim.x + threadIdx.x;
    if (idx >= 8 * 24 * 32) return;
    int lane = idx & 31;
    int nt = (idx >> 5) % 24;
    int ks = idx / (24 * 32);
    int g = lane >> 2, t = lane & 3;
    int n = nt * 8 + g;
    int k0 = ks * 16 + 2 * t;
    const float* W = (n < 64) ? Wl : ((n < 128) ? Wr : Ws);
    int wn = n & 63;
    float x0 = __ldg(W + (k0)     * 64 + wn);
    float x1 = __ldg(W + (k0 + 1) * 64 + wn);
    float x2 = __ldg(W + (k0 + 8) * 64 + wn);
    float x3 = __ldg(W + (k0 + 9) * 64 + wn);
    uint4 o;
    uint32_t h, l;
    bf2_split(x0, x1, h, l); o.x = h; o.z = l;
    bf2_split(x2, x3, h, l); o.y = h; o.w = l;
    g_wfrag[idx] = o;
}

// ---------------- K1: mma.sync bf16x3 GEMM, 128 rows x 192 cols per block ----------------
// 512 thr = 16 warps = 8 row-strips x 2 col-halves.
#define WSMEM (8 * 24 * 32 * 16)   // 98304
__global__ __launch_bounds__(512) void k_gemmT(
    const float* __restrict__ x, const float* __restrict__ skip_b, int N)
{
    extern __shared__ uint4 sB[];   // [ks][nt][lane] 16B each
    int tid = threadIdx.x;
    int warp = tid >> 5, lane = tid & 31;
    int strip = warp & 7, colhalf = warp >> 3;
    int g = lane >> 2, t = lane & 3;

    // stage B fragments
    for (int i = tid; i < 8 * 24 * 32; i += 512) {
        unsigned int da;
        asm("{ .reg .u64 u; cvta.to.shared.u64 u, %1; cvt.u32.u64 %0, u; }"
            : "=r"(da) : "l"(sB + i));
        const uint4* src = g_wfrag + i;
        asm volatile("cp.async.cg.shared.global [%0], [%1], 16;" :: "r"(da), "l"(src));
    }
    asm volatile("cp.async.commit_group;");

    int R = blockIdx.x * 128 + strip * 16;
    int rA = R + g, rB = R + 8 + g;
    bool vA = rA < N, vB = rB < N;
    const float* xA = x + (size_t)rA * 128;
    const float* xB = x + (size_t)rB * 128;

    float D[12][4];
    #pragma unroll
    for (int i = 0; i < 12; i++)
        #pragma unroll
        for (int j = 0; j < 4; j++) D[i][j] = 0.f;

    asm volatile("cp.async.wait_group 0;");
    __syncthreads();

    #pragma unroll 1
    for (int ks = 0; ks < 8; ks++) {
        int kb = ks * 16 + 2 * t;
        float2 z = make_float2(0.f, 0.f);
        float2 p0 = vA ? *(const float2*)(xA + kb)     : z;
        float2 p2 = vA ? *(const float2*)(xA + kb + 8) : z;
        float2 p1 = vB ? *(const float2*)(xB + kb)     : z;
        float2 p3 = vB ? *(const float2*)(xB + kb + 8) : z;

        uint32_t ah[4], al[4];
        bf2_split(p0.x, p0.y, ah[0], al[0]);
        bf2_split(p1.x, p1.y, ah[1], al[1]);
        bf2_split(p2.x, p2.y, ah[2], al[2]);
        bf2_split(p3.x, p3.y, ah[3], al[3]);

        const uint4* bp = sB + (ks * 24 + colhalf * 12) * 32 + lane;
        #pragma unroll
        for (int nt = 0; nt < 12; nt++) {
            uint4 B4 = bp[nt * 32];
            mma16816(D[nt], ah, B4.x, B4.y);   // Ah * Bh
            mma16816(D[nt], ah, B4.z, B4.w);   // Ah * Bl
            mma16816(D[nt], al, B4.x, B4.y);   // Al * Bh
        }
    }

    // epilogue
    #pragma unroll
    for (int nt = 0; nt < 12; nt++) {
        int cbase = (colhalf * 12 + nt) * 8;
        float* dst = (cbase < 64) ? g_xl : ((cbase < 128) ? g_xr : g_xs);
        int c = (cbase & 63) + 2 * t;
        float add0 = 0.f, add1 = 0.f;
        if (cbase >= 128) { add0 = __ldg(skip_b + c); add1 = __ldg(skip_b + c + 1); }
        if (vA) {
            float2 v; v.x = D[nt][0] + add0; v.y = D[nt][1] + add1;
            *(float2*)(dst + (size_t)rA * 64 + c) = v;
        }
        if (vB) {
            float2 v; v.x = D[nt][2] + add0; v.y = D[nt][3] + add1;
            *(float2*)(dst + (size_t)rB * 64 + c) = v;
        }
    }
}

// ---------------- K2: per-dst softmax-aggregate, no-max, 2 edges/warp, float4 ----------------
__global__ __launch_bounds__(256) void k_edge(
    const float* __restrict__ att, const float* __restrict__ conv_bias, int N, int E)
{
    int gw = (blockIdx.x * blockDim.x + threadIdx.x) >> 5;
    if (gw >= N) return;
    int lane = threadIdx.x & 31;
    int half = lane >> 4;
    int l = lane & 15;
    int d = gw;
    unsigned hmask = half ? 0xFFFF0000u : 0x0000FFFFu;

    const float4* xl4 = (const float4*)g_xl;
    float4 xr = __ldg((const float4*)g_xr + (size_t)d * 16 + l);
    float4 at = __ldg((const float4*)att + l);

    float den = 0.f, s0 = 0.f, s1 = 0.f, s2 = 0.f, s3 = 0.f;

    int e0  = g_off[d];
    int end = (d + 1 < N) ? g_off[d + 1] : E;
    int nE  = end - e0;
    int cnt = (nE - half + 1) >> 1;
    if (cnt < 0) cnt = 0;
    int base = e0 + half;

    if (half == 1) {
        float4 v = __ldg(xl4 + (size_t)d * 16 + l);
        float t0 = v.x + xr.x, t1 = v.y + xr.y, t2 = v.z + xr.z, t3 = v.w + xr.w;
        t0 = t0 > 0.f ? t0 : 0.2f * t0;
        t1 = t1 > 0.f ? t1 : 0.2f * t1;
        t2 = t2 > 0.f ? t2 : 0.2f * t2;
        t3 = t3 > 0.f ? t3 : 0.2f * t3;
        float p = fmaf(t0, at.x, fmaf(t1, at.y, fmaf(t2, at.z, t3 * at.w)));
        p += __shfl_xor_sync(hmask, p, 1);
        p += __shfl_xor_sync(hmask, p, 2);
        float ex = __expf(p);
        den += ex;
        s0 = fmaf(v.x, ex, s0);
        s1 = fmaf(v.y, ex, s1);
        s2 = fmaf(v.z, ex, s2);
        s3 = fmaf(v.w, ex, s3);
    } else {
        float p = 0.f;
        p += __shfl_xor_sync(hmask, p, 1);
        p += __shfl_xor_sync(hmask, p, 2);
    }

    #pragma unroll 4
    for (int it = 0; it < cnt; it++) {
        int src = __ldg(&g_csr[base + 2 * it]);
        float4 v = __ldg(xl4 + (size_t)src * 16 + l);
        float t0 = v.x + xr.x, t1 = v.y + xr.y, t2 = v.z + xr.z, t3 = v.w + xr.w;
        t0 = t0 > 0.f ? t0 : 0.2f * t0;
        t1 = t1 > 0.f ? t1 : 0.2f * t1;
        t2 = t2 > 0.f ? t2 : 0.2f * t2;
        t3 = t3 > 0.f ? t3 : 0.2f * t3;
        float p = fmaf(t0, at.x, fmaf(t1, at.y, fmaf(t2, at.z, t3 * at.w)));
        p += __shfl_xor_sync(hmask, p, 1);
        p += __shfl_xor_sync(hmask, p, 2);
        float ex = __expf(p);
        den += ex;
        s0 = fmaf(v.x, ex, s0);
        s1 = fmaf(v.y, ex, s1);
        s2 = fmaf(v.z, ex, s2);
        s3 = fmaf(v.w, ex, s3);
    }

    __syncwarp();
    den += __shfl_xor_sync(0xffffffffu, den, 16);
    s0  += __shfl_xor_sync(0xffffffffu, s0, 16);
    s1  += __shfl_xor_sync(0xffffffffu, s1, 16);
    s2  += __shfl_xor_sync(0xffffffffu, s2, 16);
    s3  += __shfl_xor_sync(0xffffffffu, s3, 16);

    if (half == 0) {
        float inv = 1.f / den;
        float4 cb = __ldg((const float4*)conv_bias + l);
        float4 o;
        o.x = fmaf(s0, inv, cb.x);
        o.y = fmaf(s1, inv, cb.y);
        o.z = fmaf(s2, inv, cb.z);
        o.w = fmaf(s3, inv, cb.w);
        ((float4*)g_out)[(size_t)d * 16 + l] = o;
    }
}

// ---------------- K3a: skip-branch sums (only needs gemm) ----------------
__global__ __launch_bounds__(256) void k_statsS(const int* __restrict__ batch, int N)
{
    int gid = blockIdx.x * blockDim.x + threadIdx.x;
    int ch = gid & 63;
    int slot = gid >> 6;
    int n0 = slot * 32;
    if (n0 >= N) return;
    int n1 = min(n0 + 32, N);

    int gfirst = batch[n0], glast = batch[n1 - 1];
    if (gfirst == glast) {
        float aS = 0.f, qS = 0.f;
        #pragma unroll 4
        for (int n = n0; n < n1; n++) {
            float vs = g_xs[(size_t)n * 64 + ch];
            aS += vs; qS = fmaf(vs, vs, qS);
        }
        atomicAdd(&g_sumS[gfirst * 64 + ch], aS);
        atomicAdd(&g_sqS [gfirst * 64 + ch], qS);
        if (ch == 0) atomicAdd(&g_cnt[gfirst], (float)(n1 - n0));
        return;
    }

    float aS = 0.f, qS = 0.f, ac = 0.f;
    int curg = gfirst;
    for (int n = n0; n < n1; n++) {
        int g = batch[n];
        if (g != curg) {
            atomicAdd(&g_sumS[curg * 64 + ch], aS);
            atomicAdd(&g_sqS [curg * 64 + ch], qS);
            if (ch == 0) atomicAdd(&g_cnt[curg], ac);
            aS = qS = ac = 0.f; curg = g;
        }
        float vs = g_xs[(size_t)n * 64 + ch];
        aS += vs; qS = fmaf(vs, vs, qS);
        ac += 1.f;
    }
    atomicAdd(&g_sumS[curg * 64 + ch], aS);
    atomicAdd(&g_sqS [curg * 64 + ch], qS);
    if (ch == 0) atomicAdd(&g_cnt[curg], ac);
}

// ---------------- K3b: main-branch sums (needs edge output) ----------------
__global__ __launch_bounds__(256) void k_statsM(const int* __restrict__ batch, int N)
{
    int gid = blockIdx.x * blockDim.x + threadIdx.x;
    int ch = gid & 63;
    int slot = gid >> 6;
    int n0 = slot * 32;
    if (n0 >= N) return;
    int n1 = min(n0 + 32, N);

    int gfirst = batch[n0], glast = batch[n1 - 1];
    if (gfirst == glast) {
        float aM = 0.f, qM = 0.f;
        #pragma unroll 4
        for (int n = n0; n < n1; n++) {
            float vm = g_out[(size_t)n * 64 + ch];
            aM += vm; qM = fmaf(vm, vm, qM);
        }
        atomicAdd(&g_sumM[gfirst * 64 + ch], aM);
        atomicAdd(&g_sqM [gfirst * 64 + ch], qM);
        return;
    }

    float aM = 0.f, qM = 0.f;
    int curg = gfirst;
    for (int n = n0; n < n1; n++) {
        int g = batch[n];
        if (g != curg) {
            atomicAdd(&g_sumM[curg * 64 + ch], aM);
            atomicAdd(&g_sqM [curg * 64 + ch], qM);
            aM = qM = 0.f; curg = g;
        }
        float vm = g_out[(size_t)n * 64 + ch];
        aM += vm; qM = fmaf(vm, vm, qM);
    }
    atomicAdd(&g_sumM[curg * 64 + ch], aM);
    atomicAdd(&g_sqM [curg * 64 + ch], qM);
}

// ---------------- K3c: precompute per-(graph,channel) affine coeffs ----------------
__global__ void k_prec(
    const float* __restrict__ bn_w, const float* __restrict__ bn_b, const float* __restrict__ bn_ms,
    const float* __restrict__ sn_w, const float* __restrict__ sn_b, const float* __restrict__ sn_ms)
{
    int i = blockIdx.x * blockDim.x + threadIdx.x;
    if (i >= G_NUM * 64) return;
    int g = i >> 6, ch = i & 63;
    float cntv = fmaxf(g_cnt[g], 1.f);
    float rinv = 1.f / cntv;
    float msM = bn_ms[ch], msS = sn_ms[ch];

    float meanM = g_sumM[i] * rinv;
    float eqM   = g_sqM [i] * rinv;
    float varM  = fmaxf(eqM - meanM * meanM * msM * (2.f - msM), 0.f);
    float meanS = g_sumS[i] * rinv;
    float eqS   = g_sqS [i] * rinv;
    float varS  = fmaxf(eqS - meanS * meanS * msS * (2.f - msS), 0.f);

    float cM = bn_w[ch] * rsqrtf(varM + 1e-5f);
    float cS = sn_w[ch] * rsqrtf(varS + 1e-5f);
    float C  = bn_b[ch] + sn_b[ch] - cM * meanM * msM - cS * meanS * msS;
    g_sumM[i] = cM;
    g_sumS[i] = cS;
    g_sqM [i] = C;
}

// ---------------- K4: y = cM*vm + cS*vs + C, then ELU (float4) ----------------
__global__ __launch_bounds__(256) void k_final(
    const int* __restrict__ batch, float* __restrict__ out, int N)
{
    int i = blockIdx.x * blockDim.x + threadIdx.x;
    if (i >= N * 16) return;
    int n = i >> 4, q = i & 15;
    int g = batch[n];

    float4 cM = ((const float4*)g_sumM)[g * 16 + q];
    float4 cS = ((const float4*)g_sumS)[g * 16 + q];
    float4 C  = ((const float4*)g_sqM )[g * 16 + q];
    float4 vm = ((const float4*)g_out)[i];
    float4 vs = ((const float4*)g_xs)[i];

    float4 res;
    float y;
    y = fmaf(cM.x, vm.x, fmaf(cS.x, vs.x, C.x)); res.x = (y > 0.f) ? y : (__expf(y) - 1.f);
    y = fmaf(cM.y, vm.y, fmaf(cS.y, vs.y, C.y)); res.y = (y > 0.f) ? y : (__expf(y) - 1.f);
    y = fmaf(cM.z, vm.z, fmaf(cS.z, vs.z, C.z)); res.z = (y > 0.f) ? y : (__expf(y) - 1.f);
    y = fmaf(cM.w, vm.w, fmaf(cS.w, vs.w, C.w)); res.w = (y > 0.f) ? y : (__expf(y) - 1.f);
    ((float4*)out)[i] = res;
}

// ---------------- launch (fork-join: CSR+statsS overlap GEMM+edge) ----------------
extern "C" void kernel_launch(void* const* d_in, const int* in_sizes, int n_in,
                              void* d_out, int out_size)
{
    const float* x         = (const float*)d_in[0];
    const int*   ei        = (const int*)d_in[1];
    const int*   batch     = (const int*)d_in[2];
    const float* Wl        = (const float*)d_in[3];
    const float* Wr        = (const float*)d_in[4];
    const float* att       = (const float*)d_in[5];
    const float* conv_bias = (const float*)d_in[6];
    const float* skip_W    = (const float*)d_in[7];
    const float* skip_b    = (const float*)d_in[8];
    const float* bn_w      = (const float*)d_in[9];
    const float* bn_b      = (const float*)d_in[10];
    const float* bn_ms     = (const float*)d_in[11];
    const float* sn_w      = (const float*)d_in[12];
    const float* sn_b      = (const float*)d_in[13];
    const float* sn_ms     = (const float*)d_in[14];
    float*       out       = (float*)d_out;

    int N  = in_sizes[0] / 128;
    int E  = in_sizes[1] / 2;
    int nb = (N + 1023) / 1024;

    static cudaStream_t s1 = nullptr;
    static cudaEvent_t evFork = nullptr, evJoin = nullptr, evGemm = nullptr, evS = nullptr;
    if (s1 == nullptr) {
        cudaStreamCreateWithFlags(&s1, cudaStreamNonBlocking);
        cudaEventCreateWithFlags(&evFork, cudaEventDisableTiming);
        cudaEventCreateWithFlags(&evJoin, cudaEventDisableTiming);
        cudaEventCreateWithFlags(&evGemm, cudaEventDisableTiming);
        cudaEventCreateWithFlags(&evS, cudaEventDisableTiming);
        cudaFuncSetAttribute(k_gemmT, cudaFuncAttributeMaxDynamicSharedMemorySize, WSMEM);
    }

    // fork: CSR build chain on s1
    cudaEventRecord(evFork, 0);
    cudaStreamWaitEvent(s1, evFork, 0);

    k_init <<<(N + 255) / 256, 256, 0, s1>>>(N);
    k_hist <<<(E + 255) / 256, 256, 0, s1>>>(ei, E);
    k_scan1<<<nb, 1024, 0, s1>>>(N);
    k_scan2<<<1, 1024, 0, s1>>>(nb);
    k_scan3<<<(N + 255) / 256, 256, 0, s1>>>(N);
    k_fill <<<(E + 255) / 256, 256, 0, s1>>>(ei, E);
    cudaEventRecord(evJoin, s1);

    // main: weight fragment prep + tensor-core GEMM (128 rows/block)
    k_wprep<<<(8 * 24 * 32 + 255) / 256, 256>>>(Wl, Wr, skip_W);
    k_gemmT<<<(N + 127) / 128, 512, WSMEM>>>(x, skip_b, N);
    cudaEventRecord(evGemm, 0);

    // statsS overlaps edge on side stream
    cudaStreamWaitEvent(s1, evGemm, 0);
    {
        int slots = (N + 31) / 32;
        long long threads = (long long)slots * 64;
        k_statsS<<<(unsigned)((threads + 255) / 256), 256, 0, s1>>>(batch, N);
    }
    cudaEventRecord(evS, s1);

    // join: edge needs both GEMM output and CSR
    cudaStreamWaitEvent(0, evJoin, 0);

    {   // edge: 1 warp per node
        long long threads = (long long)N * 32;
        k_edge<<<(unsigned)((threads + 255) / 256), 256>>>(att, conv_bias, N, E);
    }
    {   // statsM
        int slots = (N + 31) / 32;
        long long threads = (long long)slots * 64;
        k_statsM<<<(unsigned)((threads + 255) / 256), 256>>>(batch, N);
    }
    cudaStreamWaitEvent(0, evS, 0);
    k_prec<<<(G_NUM * 64 + 255) / 256, 256>>>(bn_w, bn_b, bn_ms, sn_w, sn_b, sn_ms);
    {   // final
        long long total = (long long)N * 16;
        k_final<<<(unsigned)((total + 255) / 256), 256>>>(batch, out, N);
    }
}